// round 10
// baseline (speedup 1.0000x reference)
#include <cuda_runtime.h>
#include <cuda_bf16.h>
#include <cuda_fp16.h>
#include <math.h>
#include <stdint.h>

// Problem constants: B=8, S=128, H=768, M=128, P = S(S+1)/2 = 8256
#define Bn 8
#define Sn 128
#define Hn 768
#define Mn 128
#define Pn 8256

// Scratch (__device__ globals; allocation-free rule)
__device__ float g_xhat[Bn*Sn*Hn];                         // (x-mean)/(var+eps)^2
__device__ float g_gc  [Bn*Sn*Hn];                         // seq @ w_gamma^T + gamma
__device__ float g_bc  [Bn*Sn*Hn];                         // seq @ w_beta^T  + beta
__device__ float g_Cmat[3*Bn*Sn*Mn];                       // bc @ W_k + bias_k
__device__ __align__(16) __half g_Wth[3*Mn*Hn];            // W_k^T fp16 [k][m][h]
__device__ __align__(16) __nv_bfloat16 g_seq_hi[Bn*Sn*Hn]; // seq split hi (cln)
__device__ __align__(16) __nv_bfloat16 g_seq_lo[Bn*Sn*Hn];
__device__ __align__(16) __nv_bfloat16 g_Wg_hi[Hn*Hn];     // w_gamma [o][h] hi
__device__ __align__(16) __nv_bfloat16 g_Wg_lo[Hn*Hn];
__device__ __align__(16) __nv_bfloat16 g_Wb_hi[Hn*Hn];     // w_beta  [o][h] hi
__device__ __align__(16) __nv_bfloat16 g_Wb_lo[Hn*Hn];

// ---------------------------------------------------------------------------
__device__ __forceinline__ uint32_t smem_u32(const void* p) {
    uint32_t a;
    asm("{ .reg .u64 t; cvta.to.shared.u64 t, %1; cvt.u32.u64 %0, t; }" : "=r"(a) : "l"(p));
    return a;
}
__device__ __forceinline__ void ldmx4(uint32_t& r0, uint32_t& r1, uint32_t& r2, uint32_t& r3,
                                      uint32_t a) {
    asm volatile("ldmatrix.sync.aligned.m8n8.x4.shared.b16 {%0,%1,%2,%3}, [%4];"
                 : "=r"(r0), "=r"(r1), "=r"(r2), "=r"(r3) : "r"(a));
}
__device__ __forceinline__ void mma_bf(float* d, const uint32_t* a, uint32_t b0, uint32_t b1) {
    asm volatile(
        "mma.sync.aligned.m16n8k16.row.col.f32.bf16.bf16.f32 "
        "{%0,%1,%2,%3},{%4,%5,%6,%7},{%8,%9},{%0,%1,%2,%3};"
        : "+f"(d[0]), "+f"(d[1]), "+f"(d[2]), "+f"(d[3])
        : "r"(a[0]), "r"(a[1]), "r"(a[2]), "r"(a[3]), "r"(b0), "r"(b1));
}
__device__ __forceinline__ void mma_fp16(float* d, const uint32_t* a, uint32_t b0, uint32_t b1) {
    asm volatile(
        "mma.sync.aligned.m16n8k16.row.col.f32.f16.f16.f32 "
        "{%0,%1,%2,%3},{%4,%5,%6,%7},{%8,%9},{%0,%1,%2,%3};"
        : "+f"(d[0]), "+f"(d[1]), "+f"(d[2]), "+f"(d[3])
        : "r"(a[0]), "r"(a[1]), "r"(a[2]), "r"(a[3]), "r"(b0), "r"(b1));
}
#define CP16(dst, src) \
    asm volatile("cp.async.cg.shared.global [%0], [%1], 16;" :: "r"(dst), "l"(src) : "memory")
#define CP_COMMIT() asm volatile("cp.async.commit_group;" ::: "memory")
#define CP_WAITG(n) asm volatile("cp.async.wait_group %0;" :: "n"(n) : "memory")

__device__ __forceinline__ float tanh_fast(float x) {
    float ax = fabsf(x);
    float e  = __expf(2.0f * ax);
    float r  = 1.0f - 2.0f / (e + 1.0f);
    return copysignf(r, x);
}

#define RS 80                      // smem row stride: 64B data + 16B pad
#define KC 32
#define NCH 24                     // 768/32
#define WTB (128 * RS)             // 10240: 128-row k-chunk tile

// ===========================================================================
// Kernel 1 (merged prep): blockIdx ranges ->
//   [0,1024): stats + xhat + seq hi/lo splits
//   [1024, 1024+4608): cln weight bf16 splits
//   [5632, 5632+1152): projection weights -> fp16 transpose
// ===========================================================================
#define NB_STATS 1024
#define NB_WCLN  4608              // 2*768*768/256
#define NB_WPROJ 1152              // 3*128*768/256

__global__ void __launch_bounds__(256) prep_kernel(
    const float* __restrict__ seq,
    const float* __restrict__ w_gamma, const float* __restrict__ w_beta,
    const float* __restrict__ w_ent,   const float* __restrict__ w_head,
    const float* __restrict__ w_tail)
{
    __shared__ float warp_s[8];
    __shared__ float stat[2];
    const int bid = blockIdx.x;
    const int tid = threadIdx.x;

    if (bid < NB_STATS) {
        const int r = bid;
        const float* x = seq + (size_t)r * Hn;
        float v0 = x[tid], v1 = x[tid + 256], v2 = x[tid + 512];
        {
            __nv_bfloat16 h0 = __float2bfloat16(v0);
            __nv_bfloat16 h1 = __float2bfloat16(v1);
            __nv_bfloat16 h2 = __float2bfloat16(v2);
            g_seq_hi[(size_t)r*Hn + tid]       = h0;
            g_seq_hi[(size_t)r*Hn + tid + 256] = h1;
            g_seq_hi[(size_t)r*Hn + tid + 512] = h2;
            g_seq_lo[(size_t)r*Hn + tid]       = __float2bfloat16(v0 - __bfloat162float(h0));
            g_seq_lo[(size_t)r*Hn + tid + 256] = __float2bfloat16(v1 - __bfloat162float(h1));
            g_seq_lo[(size_t)r*Hn + tid + 512] = __float2bfloat16(v2 - __bfloat162float(h2));
        }
        float s = v0 + v1 + v2;
        #pragma unroll
        for (int o = 16; o; o >>= 1) s += __shfl_xor_sync(0xffffffffu, s, o);
        if ((tid & 31) == 0) warp_s[tid >> 5] = s;
        __syncthreads();
        if (tid == 0) {
            float t = 0.f;
            #pragma unroll
            for (int i = 0; i < 8; i++) t += warp_s[i];
            stat[0] = t * (1.0f / (float)Hn);
        }
        __syncthreads();
        const float mean = stat[0];
        float d0 = v0 - mean, d1 = v1 - mean, d2 = v2 - mean;
        float s2 = d0*d0 + d1*d1 + d2*d2;
        #pragma unroll
        for (int o = 16; o; o >>= 1) s2 += __shfl_xor_sync(0xffffffffu, s2, o);
        if ((tid & 31) == 0) warp_s[tid >> 5] = s2;
        __syncthreads();
        if (tid == 0) {
            float t = 0.f;
            #pragma unroll
            for (int i = 0; i < 8; i++) t += warp_s[i];
            float var = t * (1.0f / (float)Hn);
            float d = var + 1e-12f;
            stat[1] = 1.0f / (d * d);             // ref quirk: (var+eps)^2, no sqrt
        }
        __syncthreads();
        const float inv = stat[1];
        float* xo = g_xhat + (size_t)r * Hn;
        xo[tid]       = d0 * inv;
        xo[tid + 256] = d1 * inv;
        xo[tid + 512] = d2 * inv;
    } else if (bid < NB_STATS + NB_WCLN) {
        int idx = (bid - NB_STATS) * 256 + tid;
        int z = idx / (Hn * Hn);
        int e = idx - z * (Hn * Hn);
        float v = (z ? w_beta : w_gamma)[e];
        __nv_bfloat16 hi = __float2bfloat16(v);
        __nv_bfloat16 lo = __float2bfloat16(v - __bfloat162float(hi));
        if (z) { g_Wb_hi[e] = hi; g_Wb_lo[e] = lo; }
        else   { g_Wg_hi[e] = hi; g_Wg_lo[e] = lo; }
    } else {
        int idx = (bid - NB_STATS - NB_WCLN) * 256 + tid;
        int k  = idx / (Mn * Hn);
        int rm = idx - k * (Mn * Hn);
        int m  = rm / Hn;
        int h  = rm - m * Hn;
        const float* W = (k == 0) ? w_ent : (k == 1) ? w_head : w_tail;
        g_Wth[idx] = __float2half(W[(size_t)h * Mn + m]);
    }
}

// ===========================================================================
// Kernel 2: cln NT GEMM via bf16x3 HMMA -> g_gc / g_bc  (64x64, grid 384)
// ===========================================================================
#define CL_ATB 5120
#define CL_WOFF (4 * CL_ATB)
#define CL_WTB 5120
#define CL_BIAS (CL_WOFF + 4 * CL_WTB)
#define CL_SMEM (CL_BIAS + 256 + 16)

__global__ void __launch_bounds__(256, 3) cln_hmma_kernel(
    const float* __restrict__ gamma, const float* __restrict__ beta)
{
    extern __shared__ __align__(128) char dsm[];
    const uint32_t sB = smem_u32(dsm);
    float* biasS = (float*)(dsm + CL_BIAS);

    const int z  = blockIdx.z;
    const __nv_bfloat16* Wh_g = z ? g_Wb_hi : g_Wg_hi;
    const __nv_bfloat16* Wl_g = z ? g_Wb_lo : g_Wg_lo;
    const float* bias = z ? beta : gamma;
    float* dst        = z ? g_bc : g_gc;

    const int r0 = blockIdx.x * 64;
    const int c0 = blockIdx.y * 64;
    const int tid  = threadIdx.x;
    const int wid  = tid >> 5;
    const int lane = tid & 31;
    const int g    = lane >> 2;
    const int tg   = lane & 3;
    const int wm   = wid >> 1, wn = wid & 1;

    if (tid < 64) biasS[tid] = bias[c0 + tid];

    float acc[4][4];
    #pragma unroll
    for (int nt = 0; nt < 4; nt++)
        #pragma unroll
        for (int r = 0; r < 4; r++) acc[nt][r] = 0.f;

    const int lrow  = (tid & 127) >> 1;
    const int fhalf = tid & 1;
    const uint32_t dro = (uint32_t)(lrow * RS + fhalf * 32);
    const bool isA = (tid < 128);

    auto fill = [&](int c, int s) {
        const int kc = c * KC;
        if (isA) {
            size_t asrc = (size_t)(r0 + lrow) * Hn + kc + fhalf * 16;
            uint32_t ad = sB + s * (2 * CL_ATB) + dro;
            CP16(ad,                (const char*)(g_seq_hi + asrc));
            CP16(ad + 16,           (const char*)(g_seq_hi + asrc + 8));
            CP16(ad + CL_ATB,       (const char*)(g_seq_lo + asrc));
            CP16(ad + CL_ATB + 16,  (const char*)(g_seq_lo + asrc + 8));
        } else {
            size_t wsrc = (size_t)(c0 + lrow) * Hn + kc + fhalf * 16;
            uint32_t wd = sB + CL_WOFF + s * (2 * CL_WTB) + dro;
            CP16(wd,                (const char*)(Wh_g + wsrc));
            CP16(wd + 16,           (const char*)(Wh_g + wsrc + 8));
            CP16(wd + CL_WTB,       (const char*)(Wl_g + wsrc));
            CP16(wd + CL_WTB + 16,  (const char*)(Wl_g + wsrc + 8));
        }
        CP_COMMIT();
    };

    const uint32_t loff = (uint32_t)(((lane & 7) + ((lane >> 3) & 1) * 8) * RS + (lane >> 4) * 16);

    fill(0, 0);
    for (int c = 0; c < NCH; ++c) {
        const int s = c & 1;
        if (c + 1 < NCH) { __syncthreads(); fill(c + 1, s ^ 1); CP_WAITG(1); }
        else             { CP_WAITG(0); }
        __syncthreads();

        const uint32_t aH = sB + s * (2 * CL_ATB);
        const uint32_t aL = aH + CL_ATB;
        const uint32_t wH = sB + CL_WOFF + s * (2 * CL_WTB);
        const uint32_t wL = wH + CL_WTB;

        #pragma unroll
        for (int ks = 0; ks < 2; ks++) {
            const uint32_t ko = ks * 32 + loff;
            uint32_t Ah[4], Al[4];
            uint32_t ab = (uint32_t)((wm * 16) * RS) + ko;
            ldmx4(Ah[0], Ah[1], Ah[2], Ah[3], aH + ab);
            ldmx4(Al[0], Al[1], Al[2], Al[3], aL + ab);
            #pragma unroll
            for (int ntp = 0; ntp < 2; ntp++) {
                uint32_t wb = (uint32_t)((wn * 32 + ntp * 16) * RS) + ko;
                uint32_t h0, h1, h2, h3, l0, l1, l2, l3;
                ldmx4(h0, h1, h2, h3, wH + wb);
                ldmx4(l0, l1, l2, l3, wL + wb);
                mma_bf(acc[2*ntp],   Ah, h0, h2);
                mma_bf(acc[2*ntp],   Ah, l0, l2);
                mma_bf(acc[2*ntp],   Al, h0, h2);
                mma_bf(acc[2*ntp+1], Ah, h1, h3);
                mma_bf(acc[2*ntp+1], Ah, l1, l3);
                mma_bf(acc[2*ntp+1], Al, h1, h3);
            }
        }
    }

    {
        const int row = r0 + wm * 16 + g;
        #pragma unroll
        for (int nt = 0; nt < 4; nt++) {
            const int cc = wn * 32 + nt * 8 + tg * 2;
            const float b0v = biasS[cc], b1v = biasS[cc + 1];
            const float* d = acc[nt];
            *(float2*)(dst + (size_t)row * Hn + c0 + cc) =
                make_float2(d[0] + b0v, d[1] + b1v);
            *(float2*)(dst + (size_t)(row + 8) * Hn + c0 + cc) =
                make_float2(d[2] + b0v, d[3] + b1v);
        }
    }
}

// ===========================================================================
// Kernel 3: cmat NN GEMM (fp32) -> g_Cmat, 16-row tiles, K-step 64, grid (64,3)
// ===========================================================================
__global__ void __launch_bounds__(256) cmat_gemm_kernel(
    const float* __restrict__ w_ent,  const float* __restrict__ b_ent,
    const float* __restrict__ w_head, const float* __restrict__ b_head,
    const float* __restrict__ w_tail, const float* __restrict__ b_tail)
{
    __shared__ float Ash[64][17];
    __shared__ float Bsh[64][132];
    const int k = blockIdx.y;
    const float* W    = (k == 0) ? w_ent : (k == 1) ? w_head : w_tail;
    const float* bias = (k == 0) ? b_ent : (k == 1) ? b_head : b_tail;
    const int r0 = blockIdx.x * 16;
    const int tid = threadIdx.x;
    const int tx = tid & 15, ty = tid >> 4;
    const int arow = tid & 15, akq = (tid >> 4) * 4;
    const int bk = tid >> 4, bm0 = (tid & 15) * 8;

    float acc[8];
    #pragma unroll
    for (int v = 0; v < 8; v++) acc[v] = 0.f;

    for (int k0 = 0; k0 < Hn; k0 += 64) {
        float4 a = *(const float4*)(g_bc + (size_t)(r0 + arow) * Hn + k0 + akq);
        Ash[akq+0][arow] = a.x; Ash[akq+1][arow] = a.y;
        Ash[akq+2][arow] = a.z; Ash[akq+3][arow] = a.w;
        #pragma unroll
        for (int rr = 0; rr < 4; rr++) {
            const float4* bp = (const float4*)(W + (size_t)(k0 + bk + rr*16) * Mn + bm0);
            *(float4*)&Bsh[bk + rr*16][bm0]     = bp[0];
            *(float4*)&Bsh[bk + rr*16][bm0 + 4] = bp[1];
        }
        __syncthreads();
        #pragma unroll
        for (int kk = 0; kk < 64; kk++) {
            float a0 = Ash[kk][ty];
            #pragma unroll
            for (int v = 0; v < 8; v++) acc[v] += a0 * Bsh[kk][tx + 16*v];
        }
        __syncthreads();
    }
    {
        int rr = r0 + ty;
        #pragma unroll
        for (int v = 0; v < 8; v++) {
            int cc = tx + 16*v;
            g_Cmat[((size_t)k * (Bn*Sn) + rr) * Mn + cc] = acc[v] + bias[cc];
        }
    }
}

// ===========================================================================
// Kernel 4: pair GEMM, fp16 HMMA, 4-stage ring, TWO chunks per barrier.
//   One CTA per (b, i, head); R = 128 - (i/32)*32 at runtime.
//   Iter t: wait, barrier, MMA(2t), fill A(2t+2), MMA(2t+1), fill A(2t+3)+W.
// ===========================================================================
#define PAIR_AOFF (4 * WTB)
#define PAIR_SMEM (4 * WTB + 4 * (128 * RS) + Hn * 4 + 512 + 64)

__global__ void __launch_bounds__(256, 2) pair_f16_all(float* __restrict__ out) {
    extern __shared__ __align__(128) char dsm[];
    const uint32_t sB = smem_u32(dsm);

    const int tid  = threadIdx.x;
    const int wid  = tid >> 5;
    const int lane = tid & 31;
    const int g    = lane >> 2;
    const int tg   = lane & 3;
    const int wn   = wid & 3;            // 4 n-warps x 32 cols
    const int wm   = wid >> 2;           // 2 m-warps
    const int i    = blockIdx.x & 127;
    const int b    = blockIdx.x >> 7;
    const int head = blockIdx.y;

    const int J0  = (i >> 5) << 5;
    const int Rr  = 128 - J0;
    const int MTr = Rr >> 5;             // 1..4
    const int ATB = Rr * RS;
    const int GOFF = PAIR_AOFF + 4 * ATB;
    const int COFF = GOFF + Hn * 4;
    float* gcs = (float*)(dsm + GOFF);
    float* cmS = (float*)(dsm + COFF);

    {
        const float* gsrc = g_gc + (size_t)(b * Sn + i) * Hn;
        for (int t = tid; t < Hn; t += 256) gcs[t] = gsrc[t];
        if (tid < 128)
            cmS[tid] = g_Cmat[((size_t)head * (Bn*Sn) + b * Sn + i) * Mn + tid];
    }
    __syncthreads();

    float acc[4][4][4];
    #pragma unroll
    for (int mt = 0; mt < 4; mt++)
        #pragma unroll
        for (int nt = 0; nt < 4; nt++)
            #pragma unroll
            for (int r = 0; r < 4; r++) acc[mt][nt][r] = 0.f;

    const int lrow = tid >> 1, fhalf = tid & 1;
    const uint32_t dro = (uint32_t)(lrow * RS + fhalf * 32);
    const float* xrow = g_xhat + (size_t)(b * Sn + J0 + lrow) * Hn;
    const bool afill = (tid < 2 * Rr);

    float4 xr0, xr1, xr2, xr3;
    auto ldx = [&](int c) {
        if (afill) {
            const float4* xp = (const float4*)(xrow + c * KC + fhalf * 16);
            xr0 = xp[0]; xr1 = xp[1]; xr2 = xp[2]; xr3 = xp[3];
        }
    };
    auto buildA = [&](int c) {
        if (afill) {
            const int s = c & 3;
            const float4* gp = (const float4*)(gcs + c * KC + fhalf * 16);
            float4 g0 = gp[0], g1 = gp[1], g2 = gp[2], g3 = gp[3];
            __half2 h[8];
            h[0] = __floats2half2_rn(xr0.x * g0.x, xr0.y * g0.y);
            h[1] = __floats2half2_rn(xr0.z * g0.z, xr0.w * g0.w);
            h[2] = __floats2half2_rn(xr1.x * g1.x, xr1.y * g1.y);
            h[3] = __floats2half2_rn(xr1.z * g1.z, xr1.w * g1.w);
            h[4] = __floats2half2_rn(xr2.x * g2.x, xr2.y * g2.y);
            h[5] = __floats2half2_rn(xr2.z * g2.z, xr2.w * g2.w);
            h[6] = __floats2half2_rn(xr3.x * g3.x, xr3.y * g3.y);
            h[7] = __floats2half2_rn(xr3.z * g3.z, xr3.w * g3.w);
            char* ab = dsm + PAIR_AOFF + s * ATB;
            *(uint4*)(ab + dro)      = *(uint4*)&h[0];
            *(uint4*)(ab + dro + 16) = *(uint4*)&h[4];
        }
    };
    auto cpW = [&](int c) {
        const int s = c & 3;
        size_t wsrc = (size_t)(head * Mn + lrow) * Hn + c * KC + fhalf * 16;
        uint32_t wd = sB + s * WTB + dro;
        CP16(wd,      (const char*)(g_Wth + wsrc));
        CP16(wd + 16, (const char*)(g_Wth + wsrc + 8));
    };

    const uint32_t loff = (uint32_t)(((lane & 7) + ((lane >> 3) & 1) * 8) * RS + (lane >> 4) * 16);
    const uint32_t mrowb = (uint32_t)(wm * MTr * 16);

    auto domma = [&](int c) {
        const int s = c & 3;
        const uint32_t aB = sB + PAIR_AOFF + s * ATB;
        const uint32_t wB = sB + s * WTB;
        #pragma unroll
        for (int ks = 0; ks < 2; ks++) {
            const uint32_t ko = ks * 32 + loff;
            uint32_t Ah[4][4];
            #pragma unroll
            for (int mt = 0; mt < 4; mt++)
                if (mt < MTr) {
                    uint32_t ab = (mrowb + mt * 16) * RS + ko;
                    ldmx4(Ah[mt][0], Ah[mt][1], Ah[mt][2], Ah[mt][3], aB + ab);
                }
            #pragma unroll
            for (int ntp = 0; ntp < 2; ntp++) {
                uint32_t wb = (uint32_t)((wn * 32 + ntp * 16) * RS) + ko;
                uint32_t h0, h1, h2, h3;
                ldmx4(h0, h1, h2, h3, wB + wb);
                #pragma unroll
                for (int mt = 0; mt < 4; mt++)
                    if (mt < MTr) {
                        mma_fp16(acc[mt][2*ntp],   Ah[mt], h0, h2);
                        mma_fp16(acc[mt][2*ntp+1], Ah[mt], h1, h3);
                    }
            }
        }
    };

    // prologue: A+W for chunks 0,1; x prefetched for chunk 2
    ldx(0); buildA(0); cpW(0); CP_COMMIT();
    ldx(1); buildA(1); cpW(1); CP_COMMIT();
    ldx(2);

    for (int t = 0; t < NCH / 2; ++t) {
        const int c0 = 2 * t, c1 = 2 * t + 1;
        CP_WAITG(0);
        __syncthreads();      // A/W for c0,c1 ready; all reads of stages c0+2,c1+2 done

        domma(c0);
        if (c0 + 2 < NCH) { buildA(c0 + 2); ldx(c0 + 3); }

        domma(c1);
        if (c1 + 2 < NCH) {
            buildA(c1 + 2);
            cpW(c0 + 2); cpW(c1 + 2); CP_COMMIT();
            if (c1 + 3 < NCH) ldx(c1 + 3);
        }
    }

    // epilogue
    const int offi = i * Sn - (i * (i - 1)) / 2;
    const size_t hb = (size_t)(head * Bn + b) * Pn;
    #pragma unroll
    for (int mt = 0; mt < 4; mt++) {
        if (mt >= MTr) break;
        const int j0r = J0 + wm * MTr * 16 + mt * 16 + g;
        #pragma unroll
        for (int nt = 0; nt < 4; nt++) {
            const int m = wn * 32 + nt * 8 + tg * 2;
            const float cm0 = cmS[m], cm1 = cmS[m + 1];
            const float* d = acc[mt][nt];
            if (j0r >= i) {
                *(float2*)(out + (hb + (size_t)(offi - i + j0r)) * Mn + m) =
                    make_float2(tanh_fast(d[0] + cm0), tanh_fast(d[1] + cm1));
            }
            const int j1r = j0r + 8;
            if (j1r >= i) {
                *(float2*)(out + (hb + (size_t)(offi - i + j1r)) * Mn + m) =
                    make_float2(tanh_fast(d[2] + cm0), tanh_fast(d[3] + cm1));
            }
        }
    }
}

// ===========================================================================
extern "C" void kernel_launch(void* const* d_in, const int* in_sizes, int n_in,
                              void* d_out, int out_size) {
    (void)in_sizes; (void)n_in; (void)out_size;
    const float* seq     = (const float*)d_in[0];
    const float* gamma   = (const float*)d_in[1];
    const float* beta    = (const float*)d_in[2];
    const float* w_beta  = (const float*)d_in[3];
    const float* w_gamma = (const float*)d_in[4];
    const float* w_ent   = (const float*)d_in[5];
    const float* b_ent   = (const float*)d_in[6];
    const float* w_head  = (const float*)d_in[7];
    const float* b_head  = (const float*)d_in[8];
    const float* w_tail  = (const float*)d_in[9];
    const float* b_tail  = (const float*)d_in[10];
    float* out = (float*)d_out;

    cudaFuncSetAttribute(cln_hmma_kernel,
                         cudaFuncAttributeMaxDynamicSharedMemorySize, CL_SMEM);
    cudaFuncSetAttribute(pair_f16_all,
                         cudaFuncAttributeMaxDynamicSharedMemorySize, PAIR_SMEM);

    prep_kernel<<<NB_STATS + NB_WCLN + NB_WPROJ, 256>>>(
        seq, w_gamma, w_beta, w_ent, w_head, w_tail);
    cln_hmma_kernel<<<dim3(16, 12, 2), 256, CL_SMEM>>>(gamma, beta);
    cmat_gemm_kernel<<<dim3(64, 3), 256>>>(w_ent, b_ent, w_head, b_head, w_tail, b_tail);
    pair_f16_all<<<dim3(1024, 3), 256, PAIR_SMEM>>>(out);
}

// round 12
// speedup vs baseline: 1.0276x; 1.0276x over previous
#include <cuda_runtime.h>
#include <cuda_bf16.h>
#include <cuda_fp16.h>
#include <math.h>
#include <stdint.h>

// Problem constants: B=8, S=128, H=768, M=128, P = S(S+1)/2 = 8256
#define Bn 8
#define Sn 128
#define Hn 768
#define Mn 128
#define Pn 8256

// Scratch (__device__ globals; allocation-free rule)
__device__ float g_xhat[Bn*Sn*Hn];                         // (x-mean)/(var+eps)^2
__device__ float g_gc  [Bn*Sn*Hn];                         // seq @ w_gamma^T + gamma
__device__ float g_bc  [Bn*Sn*Hn];                         // seq @ w_beta^T  + beta
__device__ float g_Cmat[3*Bn*Sn*Mn];                       // bc @ W_k + bias_k
__device__ __align__(16) __half g_Wth[3*Mn*Hn];            // W_k^T fp16 [k][m][h]
__device__ __align__(16) __half g_Ap[100663296];           // A fp16 [(b,i)][j][h] (201MB)
__device__ __align__(16) __nv_bfloat16 g_seq_hi[Bn*Sn*Hn]; // seq split hi (cln)
__device__ __align__(16) __nv_bfloat16 g_seq_lo[Bn*Sn*Hn];
__device__ __align__(16) __nv_bfloat16 g_Wg_hi[Hn*Hn];     // w_gamma [o][h] hi
__device__ __align__(16) __nv_bfloat16 g_Wg_lo[Hn*Hn];
__device__ __align__(16) __nv_bfloat16 g_Wb_hi[Hn*Hn];     // w_beta  [o][h] hi
__device__ __align__(16) __nv_bfloat16 g_Wb_lo[Hn*Hn];

// ---------------------------------------------------------------------------
__device__ __forceinline__ uint32_t smem_u32(const void* p) {
    uint32_t a;
    asm("{ .reg .u64 t; cvta.to.shared.u64 t, %1; cvt.u32.u64 %0, t; }" : "=r"(a) : "l"(p));
    return a;
}
__device__ __forceinline__ void ldmx4(uint32_t& r0, uint32_t& r1, uint32_t& r2, uint32_t& r3,
                                      uint32_t a) {
    asm volatile("ldmatrix.sync.aligned.m8n8.x4.shared.b16 {%0,%1,%2,%3}, [%4];"
                 : "=r"(r0), "=r"(r1), "=r"(r2), "=r"(r3) : "r"(a));
}
__device__ __forceinline__ void mma_bf(float* d, const uint32_t* a, uint32_t b0, uint32_t b1) {
    asm volatile(
        "mma.sync.aligned.m16n8k16.row.col.f32.bf16.bf16.f32 "
        "{%0,%1,%2,%3},{%4,%5,%6,%7},{%8,%9},{%0,%1,%2,%3};"
        : "+f"(d[0]), "+f"(d[1]), "+f"(d[2]), "+f"(d[3])
        : "r"(a[0]), "r"(a[1]), "r"(a[2]), "r"(a[3]), "r"(b0), "r"(b1));
}
__device__ __forceinline__ void mma_fp16(float* d, const uint32_t* a, uint32_t b0, uint32_t b1) {
    asm volatile(
        "mma.sync.aligned.m16n8k16.row.col.f32.f16.f16.f32 "
        "{%0,%1,%2,%3},{%4,%5,%6,%7},{%8,%9},{%0,%1,%2,%3};"
        : "+f"(d[0]), "+f"(d[1]), "+f"(d[2]), "+f"(d[3])
        : "r"(a[0]), "r"(a[1]), "r"(a[2]), "r"(a[3]), "r"(b0), "r"(b1));
}
#define CP16(dst, src) \
    asm volatile("cp.async.cg.shared.global [%0], [%1], 16;" :: "r"(dst), "l"(src) : "memory")
#define CP_COMMIT() asm volatile("cp.async.commit_group;" ::: "memory")
#define CP_WAITG(n) asm volatile("cp.async.wait_group %0;" :: "n"(n) : "memory")

__device__ __forceinline__ float tanh_fast(float x) {
    float ax = fabsf(x);
    float e  = __expf(2.0f * ax);
    float r  = 1.0f - 2.0f / (e + 1.0f);
    return copysignf(r, x);
}

#define RS 80                      // smem row stride: 64B data + 16B pad
#define KC 32
#define NCH 24                     // 768/32
#define WTB (128 * RS)             // 10240: 128-row k-chunk tile

// ===========================================================================
// Kernel 1 (merged prep): blockIdx ranges -> stats / cln wsplit / proj fp16
// ===========================================================================
#define NB_STATS 1024
#define NB_WCLN  4608
#define NB_WPROJ 1152

__global__ void __launch_bounds__(256) prep_kernel(
    const float* __restrict__ seq,
    const float* __restrict__ w_gamma, const float* __restrict__ w_beta,
    const float* __restrict__ w_ent,   const float* __restrict__ w_head,
    const float* __restrict__ w_tail)
{
    __shared__ float warp_s[8];
    __shared__ float stat[2];
    const int bid = blockIdx.x;
    const int tid = threadIdx.x;

    if (bid < NB_STATS) {
        const int r = bid;
        const float* x = seq + (size_t)r * Hn;
        float v0 = x[tid], v1 = x[tid + 256], v2 = x[tid + 512];
        {
            __nv_bfloat16 h0 = __float2bfloat16(v0);
            __nv_bfloat16 h1 = __float2bfloat16(v1);
            __nv_bfloat16 h2 = __float2bfloat16(v2);
            g_seq_hi[(size_t)r*Hn + tid]       = h0;
            g_seq_hi[(size_t)r*Hn + tid + 256] = h1;
            g_seq_hi[(size_t)r*Hn + tid + 512] = h2;
            g_seq_lo[(size_t)r*Hn + tid]       = __float2bfloat16(v0 - __bfloat162float(h0));
            g_seq_lo[(size_t)r*Hn + tid + 256] = __float2bfloat16(v1 - __bfloat162float(h1));
            g_seq_lo[(size_t)r*Hn + tid + 512] = __float2bfloat16(v2 - __bfloat162float(h2));
        }
        float s = v0 + v1 + v2;
        #pragma unroll
        for (int o = 16; o; o >>= 1) s += __shfl_xor_sync(0xffffffffu, s, o);
        if ((tid & 31) == 0) warp_s[tid >> 5] = s;
        __syncthreads();
        if (tid == 0) {
            float t = 0.f;
            #pragma unroll
            for (int i = 0; i < 8; i++) t += warp_s[i];
            stat[0] = t * (1.0f / (float)Hn);
        }
        __syncthreads();
        const float mean = stat[0];
        float d0 = v0 - mean, d1 = v1 - mean, d2 = v2 - mean;
        float s2 = d0*d0 + d1*d1 + d2*d2;
        #pragma unroll
        for (int o = 16; o; o >>= 1) s2 += __shfl_xor_sync(0xffffffffu, s2, o);
        if ((tid & 31) == 0) warp_s[tid >> 5] = s2;
        __syncthreads();
        if (tid == 0) {
            float t = 0.f;
            #pragma unroll
            for (int i = 0; i < 8; i++) t += warp_s[i];
            float var = t * (1.0f / (float)Hn);
            float d = var + 1e-12f;
            stat[1] = 1.0f / (d * d);             // ref quirk: (var+eps)^2, no sqrt
        }
        __syncthreads();
        const float inv = stat[1];
        float* xo = g_xhat + (size_t)r * Hn;
        xo[tid]       = d0 * inv;
        xo[tid + 256] = d1 * inv;
        xo[tid + 512] = d2 * inv;
    } else if (bid < NB_STATS + NB_WCLN) {
        int idx = (bid - NB_STATS) * 256 + tid;
        int z = idx / (Hn * Hn);
        int e = idx - z * (Hn * Hn);
        float v = (z ? w_beta : w_gamma)[e];
        __nv_bfloat16 hi = __float2bfloat16(v);
        __nv_bfloat16 lo = __float2bfloat16(v - __bfloat162float(hi));
        if (z) { g_Wb_hi[e] = hi; g_Wb_lo[e] = lo; }
        else   { g_Wg_hi[e] = hi; g_Wg_lo[e] = lo; }
    } else {
        int idx = (bid - NB_STATS - NB_WCLN) * 256 + tid;
        int k  = idx / (Mn * Hn);
        int rm = idx - k * (Mn * Hn);
        int m  = rm / Hn;
        int h  = rm - m * Hn;
        const float* W = (k == 0) ? w_ent : (k == 1) ? w_head : w_tail;
        g_Wth[idx] = __float2half(W[(size_t)h * Mn + m]);
    }
}

// ===========================================================================
// Kernel 2: cln NT GEMM via bf16x3 HMMA -> g_gc / g_bc
//   64x64 tiles, 3-stage ring, ONE barrier per chunk; 3 CTAs/SM.
// ===========================================================================
#define CL_ATB 5120
#define CL_AST (2 * CL_ATB)                // 10240 per stage (hi+lo)
#define CL_WOFF (3 * CL_AST)               // 30720
#define CL_WST (2 * CL_ATB)
#define CL_BIAS (CL_WOFF + 3 * CL_WST)     // 61440
#define CL_SMEM (CL_BIAS + 256 + 16)

__global__ void __launch_bounds__(256, 3) cln_hmma_kernel(
    const float* __restrict__ gamma, const float* __restrict__ beta)
{
    extern __shared__ __align__(128) char dsm[];
    const uint32_t sB = smem_u32(dsm);
    float* biasS = (float*)(dsm + CL_BIAS);

    const int z  = blockIdx.z;
    const __nv_bfloat16* Wh_g = z ? g_Wb_hi : g_Wg_hi;
    const __nv_bfloat16* Wl_g = z ? g_Wb_lo : g_Wg_lo;
    const float* bias = z ? beta : gamma;
    float* dst        = z ? g_bc : g_gc;

    const int r0 = blockIdx.x * 64;
    const int c0 = blockIdx.y * 64;
    const int tid  = threadIdx.x;
    const int wid  = tid >> 5;
    const int lane = tid & 31;
    const int g    = lane >> 2;
    const int tg   = lane & 3;
    const int wm   = wid >> 1, wn = wid & 1;

    if (tid < 64) biasS[tid] = bias[c0 + tid];

    float acc[4][4];
    #pragma unroll
    for (int nt = 0; nt < 4; nt++)
        #pragma unroll
        for (int r = 0; r < 4; r++) acc[nt][r] = 0.f;

    const int lrow  = (tid & 127) >> 1;
    const int fhalf = tid & 1;
    const uint32_t dro = (uint32_t)(lrow * RS + fhalf * 32);
    const bool isA = (tid < 128);

    auto fill = [&](int c) {
        const int s = c % 3;
        const int kc = c * KC;
        if (isA) {
            size_t asrc = (size_t)(r0 + lrow) * Hn + kc + fhalf * 16;
            uint32_t ad = sB + s * CL_AST + dro;
            CP16(ad,                (const char*)(g_seq_hi + asrc));
            CP16(ad + 16,           (const char*)(g_seq_hi + asrc + 8));
            CP16(ad + CL_ATB,       (const char*)(g_seq_lo + asrc));
            CP16(ad + CL_ATB + 16,  (const char*)(g_seq_lo + asrc + 8));
        } else {
            size_t wsrc = (size_t)(c0 + lrow) * Hn + kc + fhalf * 16;
            uint32_t wd = sB + CL_WOFF + s * CL_WST + dro;
            CP16(wd,                (const char*)(Wh_g + wsrc));
            CP16(wd + 16,           (const char*)(Wh_g + wsrc + 8));
            CP16(wd + CL_ATB,       (const char*)(Wl_g + wsrc));
            CP16(wd + CL_ATB + 16,  (const char*)(Wl_g + wsrc + 8));
        }
        CP_COMMIT();
    };

    const uint32_t loff = (uint32_t)(((lane & 7) + ((lane >> 3) & 1) * 8) * RS + (lane >> 4) * 16);

    fill(0);
    fill(1);
    for (int c = 0; c < NCH; ++c) {
        const int s = c % 3;
        if (c == NCH - 1) { CP_WAITG(0); } else { CP_WAITG(1); }
        __syncthreads();
        if (c + 2 < NCH) fill(c + 2);

        const uint32_t aH = sB + s * CL_AST;
        const uint32_t aL = aH + CL_ATB;
        const uint32_t wH = sB + CL_WOFF + s * CL_WST;
        const uint32_t wL = wH + CL_ATB;

        #pragma unroll
        for (int ks = 0; ks < 2; ks++) {
            const uint32_t ko = ks * 32 + loff;
            uint32_t Ah[4], Al[4];
            uint32_t ab = (uint32_t)((wm * 16) * RS) + ko;
            ldmx4(Ah[0], Ah[1], Ah[2], Ah[3], aH + ab);
            ldmx4(Al[0], Al[1], Al[2], Al[3], aL + ab);
            #pragma unroll
            for (int ntp = 0; ntp < 2; ntp++) {
                uint32_t wb = (uint32_t)((wn * 32 + ntp * 16) * RS) + ko;
                uint32_t h0, h1, h2, h3, l0, l1, l2, l3;
                ldmx4(h0, h1, h2, h3, wH + wb);
                ldmx4(l0, l1, l2, l3, wL + wb);
                mma_bf(acc[2*ntp],   Ah, h0, h2);
                mma_bf(acc[2*ntp],   Ah, l0, l2);
                mma_bf(acc[2*ntp],   Al, h0, h2);
                mma_bf(acc[2*ntp+1], Ah, h1, h3);
                mma_bf(acc[2*ntp+1], Ah, l1, l3);
                mma_bf(acc[2*ntp+1], Al, h1, h3);
            }
        }
    }

    {
        const int row = r0 + wm * 16 + g;
        #pragma unroll
        for (int nt = 0; nt < 4; nt++) {
            const int cc = wn * 32 + nt * 8 + tg * 2;
            const float b0v = biasS[cc], b1v = biasS[cc + 1];
            const float* d = acc[nt];
            *(float2*)(dst + (size_t)row * Hn + c0 + cc) =
                make_float2(d[0] + b0v, d[1] + b1v);
            *(float2*)(dst + (size_t)(row + 8) * Hn + c0 + cc) =
                make_float2(d[2] + b0v, d[3] + b1v);
        }
    }
}

// ===========================================================================
// Kernel 3: cmat NN GEMM (fp32) -> g_Cmat, 16-row tiles, K-step 64, grid (64,3)
// ===========================================================================
__global__ void __launch_bounds__(256) cmat_gemm_kernel(
    const float* __restrict__ w_ent,  const float* __restrict__ b_ent,
    const float* __restrict__ w_head, const float* __restrict__ b_head,
    const float* __restrict__ w_tail, const float* __restrict__ b_tail)
{
    __shared__ float Ash[64][17];
    __shared__ float Bsh[64][132];
    const int k = blockIdx.y;
    const float* W    = (k == 0) ? w_ent : (k == 1) ? w_head : w_tail;
    const float* bias = (k == 0) ? b_ent : (k == 1) ? b_head : b_tail;
    const int r0 = blockIdx.x * 16;
    const int tid = threadIdx.x;
    const int tx = tid & 15, ty = tid >> 4;
    const int arow = tid & 15, akq = (tid >> 4) * 4;
    const int bk = tid >> 4, bm0 = (tid & 15) * 8;

    float acc[8];
    #pragma unroll
    for (int v = 0; v < 8; v++) acc[v] = 0.f;

    for (int k0 = 0; k0 < Hn; k0 += 64) {
        float4 a = *(const float4*)(g_bc + (size_t)(r0 + arow) * Hn + k0 + akq);
        Ash[akq+0][arow] = a.x; Ash[akq+1][arow] = a.y;
        Ash[akq+2][arow] = a.z; Ash[akq+3][arow] = a.w;
        #pragma unroll
        for (int rr = 0; rr < 4; rr++) {
            const float4* bp = (const float4*)(W + (size_t)(k0 + bk + rr*16) * Mn + bm0);
            *(float4*)&Bsh[bk + rr*16][bm0]     = bp[0];
            *(float4*)&Bsh[bk + rr*16][bm0 + 4] = bp[1];
        }
        __syncthreads();
        #pragma unroll
        for (int kk = 0; kk < 64; kk++) {
            float a0 = Ash[kk][ty];
            #pragma unroll
            for (int v = 0; v < 8; v++) acc[v] += a0 * Bsh[kk][tx + 16*v];
        }
        __syncthreads();
    }
    {
        int rr = r0 + ty;
        #pragma unroll
        for (int v = 0; v < 8; v++) {
            int cc = tx + 16*v;
            g_Cmat[((size_t)k * (Bn*Sn) + rr) * Mn + cc] = acc[v] + bias[cc];
        }
    }
}

// ===========================================================================
// Kernel 3b: abuild -> A fp16 per (b,i): A[j,h] = fp16(xhat[b,j,h]*gc[b,i,h])
//   grid (1024, 4): y = quarter of trimmed rows. Bit-identical to old buildA.
// ===========================================================================
__global__ void __launch_bounds__(256) abuild_kernel() {
    const int pid = blockIdx.x;            // b*128 + i
    const int i = pid & 127;
    const int J0 = (i >> 5) << 5;
    const int Rq = (128 - J0) >> 2;
    const int j0 = J0 + blockIdx.y * Rq;
    const int b = pid >> 7;
    const int tid = threadIdx.x;
    const float* gcrow = g_gc + (size_t)pid * Hn;
    for (int jr = 0; jr < Rq; jr++) {
        const int j = j0 + jr;
        const float* xr = g_xhat + ((size_t)b * Sn + j) * Hn;
        __half* ap = g_Ap + ((size_t)pid * Sn + j) * Hn;
        for (int h = tid * 2; h < Hn; h += 512) {
            float2 x  = *(const float2*)(xr + h);
            float2 gg = *(const float2*)(gcrow + h);
            *(__half2*)(ap + h) = __floats2half2_rn(x.x * gg.x, x.y * gg.y);
        }
    }
}

// ===========================================================================
// Kernel 4: pair GEMM — pure fp16 HMMA, both operands via cp.async.
//   grid (3, 1024): x=head (adjacent for A L2 reuse), y=(b,i).
//   Template MT = R/32; 4-stage ring, one barrier per 2 chunks,
//   fills issued right after the barrier (full MMA phase of latency).
// ===========================================================================
#define P_WOFF 512                          // cmS first (512B)
#define P_AOFF (512 + 4 * WTB)              // 41472
#define PAIR_SMEM (P_AOFF + 4 * 128 * RS + 64)

template<int MT>
__device__ __forceinline__ void pair_main(
    float* __restrict__ out, char* dsm, uint32_t sB,
    int tid, int b, int i, int head, float* cmS)
{
    constexpr int R   = MT * 32;
    constexpr int ATB = R * RS;
    const int J0 = 128 - R;

    const int wid  = tid >> 5;
    const int lane = tid & 31;
    const int g    = lane >> 2;
    const int tg   = lane & 3;
    const int wn   = wid & 3;              // 4 n-warps x 32 cols
    const int wm   = wid >> 2;             // 2 m-warps x MT*16 rows

    float acc[MT][4][4];
    #pragma unroll
    for (int mt = 0; mt < MT; mt++)
        #pragma unroll
        for (int nt = 0; nt < 4; nt++)
            #pragma unroll
            for (int r = 0; r < 4; r++) acc[mt][nt][r] = 0.f;

    const int lrow = tid >> 1, fhalf = tid & 1;
    const uint32_t dro = (uint32_t)(lrow * RS + fhalf * 32);
    const bool doA = (tid < 2 * R);
    const __half* wbase = g_Wth + (size_t)(head * Mn + lrow) * Hn + fhalf * 16;
    const __half* abase = g_Ap + ((size_t)(b * Sn + i) * Sn + J0 + lrow) * Hn + fhalf * 16;

    auto fill = [&](int c) {
        const int s = c & 3;
        uint32_t wd = sB + P_WOFF + s * WTB + dro;
        CP16(wd,      (const char*)(wbase + c * KC));
        CP16(wd + 16, (const char*)(wbase + c * KC + 8));
        if (doA) {
            uint32_t ad = sB + P_AOFF + s * ATB + dro;
            CP16(ad,      (const char*)(abase + c * KC));
            CP16(ad + 16, (const char*)(abase + c * KC + 8));
        }
        CP_COMMIT();
    };

    const uint32_t loff = (uint32_t)(((lane & 7) + ((lane >> 3) & 1) * 8) * RS + (lane >> 4) * 16);
    const uint32_t mrowb = (uint32_t)(wm * MT * 16);

    auto domma = [&](int c) {
        const int s = c & 3;
        const uint32_t aB = sB + P_AOFF + s * ATB;
        const uint32_t wB = sB + P_WOFF + s * WTB;
        #pragma unroll
        for (int ks = 0; ks < 2; ks++) {
            const uint32_t ko = ks * 32 + loff;
            uint32_t Ah[MT][4];
            #pragma unroll
            for (int mt = 0; mt < MT; mt++) {
                uint32_t ab = (mrowb + mt * 16) * RS + ko;
                ldmx4(Ah[mt][0], Ah[mt][1], Ah[mt][2], Ah[mt][3], aB + ab);
            }
            #pragma unroll
            for (int ntp = 0; ntp < 2; ntp++) {
                uint32_t wb = (uint32_t)((wn * 32 + ntp * 16) * RS) + ko;
                uint32_t h0, h1, h2, h3;
                ldmx4(h0, h1, h2, h3, wB + wb);
                #pragma unroll
                for (int mt = 0; mt < MT; mt++) {
                    mma_fp16(acc[mt][2*ntp],   Ah[mt], h0, h2);
                    mma_fp16(acc[mt][2*ntp+1], Ah[mt], h1, h3);
                }
            }
        }
    };

    fill(0);
    fill(1);
    for (int t = 0; t < NCH / 2; ++t) {
        const int c0 = 2 * t, c1 = 2 * t + 1;
        CP_WAITG(0);
        __syncthreads();
        if (c0 + 2 < NCH) { fill(c0 + 2); fill(c0 + 3); }
        domma(c0);
        domma(c1);
    }

    // epilogue
    const int offi = i * Sn - (i * (i - 1)) / 2;
    const size_t hb = (size_t)(head * Bn + b) * Pn;
    #pragma unroll
    for (int mt = 0; mt < MT; mt++) {
        const int j0r = J0 + wm * MT * 16 + mt * 16 + g;
        #pragma unroll
        for (int nt = 0; nt < 4; nt++) {
            const int m = wn * 32 + nt * 8 + tg * 2;
            const float cm0 = cmS[m], cm1 = cmS[m + 1];
            const float* d = acc[mt][nt];
            if (j0r >= i) {
                *(float2*)(out + (hb + (size_t)(offi - i + j0r)) * Mn + m) =
                    make_float2(tanh_fast(d[0] + cm0), tanh_fast(d[1] + cm1));
            }
            const int j1r = j0r + 8;
            if (j1r >= i) {
                *(float2*)(out + (hb + (size_t)(offi - i + j1r)) * Mn + m) =
                    make_float2(tanh_fast(d[2] + cm0), tanh_fast(d[3] + cm1));
            }
        }
    }
}

__global__ void __launch_bounds__(256, 2) pair_f16_all(float* __restrict__ out) {
    extern __shared__ __align__(128) char dsm[];
    const uint32_t sB = smem_u32(dsm);
    const int tid  = threadIdx.x;
    const int head = blockIdx.x;
    const int bi   = blockIdx.y;
    const int b    = bi >> 7;
    const int i    = bi & 127;
    float* cmS = (float*)dsm;

    if (tid < 128)
        cmS[tid] = g_Cmat[((size_t)head * (Bn*Sn) + bi) * Mn + tid];
    // cmS visibility covered by first mainloop barrier

    switch (i >> 5) {
        case 0: pair_main<4>(out, dsm, sB, tid, b, i, head, cmS); break;
        case 1: pair_main<3>(out, dsm, sB, tid, b, i, head, cmS); break;
        case 2: pair_main<2>(out, dsm, sB, tid, b, i, head, cmS); break;
        default: pair_main<1>(out, dsm, sB, tid, b, i, head, cmS); break;
    }
}

// ===========================================================================
extern "C" void kernel_launch(void* const* d_in, const int* in_sizes, int n_in,
                              void* d_out, int out_size) {
    (void)in_sizes; (void)n_in; (void)out_size;
    const float* seq     = (const float*)d_in[0];
    const float* gamma   = (const float*)d_in[1];
    const float* beta    = (const float*)d_in[2];
    const float* w_beta  = (const float*)d_in[3];
    const float* w_gamma = (const float*)d_in[4];
    const float* w_ent   = (const float*)d_in[5];
    const float* b_ent   = (const float*)d_in[6];
    const float* w_head  = (const float*)d_in[7];
    const float* b_head  = (const float*)d_in[8];
    const float* w_tail  = (const float*)d_in[9];
    const float* b_tail  = (const float*)d_in[10];
    float* out = (float*)d_out;

    cudaFuncSetAttribute(cln_hmma_kernel,
                         cudaFuncAttributeMaxDynamicSharedMemorySize, CL_SMEM);
    cudaFuncSetAttribute(pair_f16_all,
                         cudaFuncAttributeMaxDynamicSharedMemorySize, PAIR_SMEM);

    prep_kernel<<<NB_STATS + NB_WCLN + NB_WPROJ, 256>>>(
        seq, w_gamma, w_beta, w_ent, w_head, w_tail);
    cln_hmma_kernel<<<dim3(16, 12, 2), 256, CL_SMEM>>>(gamma, beta);
    cmat_gemm_kernel<<<dim3(64, 3), 256>>>(w_ent, b_ent, w_head, b_head, w_tail, b_tail);
    abuild_kernel<<<dim3(1024, 4), 256>>>();
    pair_f16_all<<<dim3(3, 1024), 256, PAIR_SMEM>>>(out);
}

// round 14
// speedup vs baseline: 1.1608x; 1.1296x over previous
#include <cuda_runtime.h>
#include <cuda_bf16.h>
#include <cuda_fp16.h>
#include <math.h>
#include <stdint.h>

// Problem constants: B=8, S=128, H=768, M=128, P = S(S+1)/2 = 8256
#define Bn 8
#define Sn 128
#define Hn 768
#define Mn 128
#define Pn 8256

// Scratch (__device__ globals; allocation-free rule)
__device__ float g_xhat[Bn*Sn*Hn];                         // (x-mean)/(var+eps)^2
__device__ float g_gc  [Bn*Sn*Hn];                         // seq @ w_gamma^T + gamma
__device__ float g_bc  [Bn*Sn*Hn];                         // seq @ w_beta^T  + beta
__device__ float g_Cmat[3*Bn*Sn*Mn];                       // bc @ W_k + bias_k
__device__ __align__(16) __half g_Wth[3*Mn*Hn];            // W_k^T fp16 [k][m][h]
__device__ __align__(16) __half g_Ap[100663296];           // A fp16 [(b,i)][j][h]
__device__ __align__(16) __nv_bfloat16 g_seq_hi[Bn*Sn*Hn]; // seq split hi (cln)
__device__ __align__(16) __nv_bfloat16 g_seq_lo[Bn*Sn*Hn];
__device__ __align__(16) __nv_bfloat16 g_Wg_hi[Hn*Hn];
__device__ __align__(16) __nv_bfloat16 g_Wg_lo[Hn*Hn];
__device__ __align__(16) __nv_bfloat16 g_Wb_hi[Hn*Hn];
__device__ __align__(16) __nv_bfloat16 g_Wb_lo[Hn*Hn];

// ---------------------------------------------------------------------------
__device__ __forceinline__ uint32_t smem_u32(const void* p) {
    uint32_t a;
    asm("{ .reg .u64 t; cvta.to.shared.u64 t, %1; cvt.u32.u64 %0, t; }" : "=r"(a) : "l"(p));
    return a;
}
__device__ __forceinline__ void ldmx4(uint32_t& r0, uint32_t& r1, uint32_t& r2, uint32_t& r3,
                                      uint32_t a) {
    asm volatile("ldmatrix.sync.aligned.m8n8.x4.shared.b16 {%0,%1,%2,%3}, [%4];"
                 : "=r"(r0), "=r"(r1), "=r"(r2), "=r"(r3) : "r"(a));
}
__device__ __forceinline__ void mma_bf(float* d, const uint32_t* a, uint32_t b0, uint32_t b1) {
    asm volatile(
        "mma.sync.aligned.m16n8k16.row.col.f32.bf16.bf16.f32 "
        "{%0,%1,%2,%3},{%4,%5,%6,%7},{%8,%9},{%0,%1,%2,%3};"
        : "+f"(d[0]), "+f"(d[1]), "+f"(d[2]), "+f"(d[3])
        : "r"(a[0]), "r"(a[1]), "r"(a[2]), "r"(a[3]), "r"(b0), "r"(b1));
}
__device__ __forceinline__ void mma_fp16(float* d, const uint32_t* a, uint32_t b0, uint32_t b1) {
    asm volatile(
        "mma.sync.aligned.m16n8k16.row.col.f32.f16.f16.f32 "
        "{%0,%1,%2,%3},{%4,%5,%6,%7},{%8,%9},{%0,%1,%2,%3};"
        : "+f"(d[0]), "+f"(d[1]), "+f"(d[2]), "+f"(d[3])
        : "r"(a[0]), "r"(a[1]), "r"(a[2]), "r"(a[3]), "r"(b0), "r"(b1));
}
#define CP16(dst, src) \
    asm volatile("cp.async.cg.shared.global [%0], [%1], 16;" :: "r"(dst), "l"(src) : "memory")
#define CP_COMMIT() asm volatile("cp.async.commit_group;" ::: "memory")
#define CP_WAITG(n) asm volatile("cp.async.wait_group %0;" :: "n"(n) : "memory")

__device__ __forceinline__ float tanh_fast(float x) {
    float ax = fabsf(x);
    float e  = __expf(2.0f * ax);
    float r  = 1.0f - 2.0f / (e + 1.0f);
    return copysignf(r, x);
}

#define RS 80                      // smem row stride: 64B data + 16B pad
#define KC 32
#define NCH 24                     // 768/32
#define WTB (128 * RS)             // 10240

// ===========================================================================
// Kernel 1 (merged prep): stats / cln wsplit / proj fp16
// ===========================================================================
#define NB_STATS 1024
#define NB_WCLN  4608
#define NB_WPROJ 1152

__global__ void __launch_bounds__(256) prep_kernel(
    const float* __restrict__ seq,
    const float* __restrict__ w_gamma, const float* __restrict__ w_beta,
    const float* __restrict__ w_ent,   const float* __restrict__ w_head,
    const float* __restrict__ w_tail)
{
    __shared__ float warp_s[8];
    __shared__ float stat[2];
    const int bid = blockIdx.x;
    const int tid = threadIdx.x;

    if (bid < NB_STATS) {
        const int r = bid;
        const float* x = seq + (size_t)r * Hn;
        float v0 = x[tid], v1 = x[tid + 256], v2 = x[tid + 512];
        {
            __nv_bfloat16 h0 = __float2bfloat16(v0);
            __nv_bfloat16 h1 = __float2bfloat16(v1);
            __nv_bfloat16 h2 = __float2bfloat16(v2);
            g_seq_hi[(size_t)r*Hn + tid]       = h0;
            g_seq_hi[(size_t)r*Hn + tid + 256] = h1;
            g_seq_hi[(size_t)r*Hn + tid + 512] = h2;
            g_seq_lo[(size_t)r*Hn + tid]       = __float2bfloat16(v0 - __bfloat162float(h0));
            g_seq_lo[(size_t)r*Hn + tid + 256] = __float2bfloat16(v1 - __bfloat162float(h1));
            g_seq_lo[(size_t)r*Hn + tid + 512] = __float2bfloat16(v2 - __bfloat162float(h2));
        }
        float s = v0 + v1 + v2;
        #pragma unroll
        for (int o = 16; o; o >>= 1) s += __shfl_xor_sync(0xffffffffu, s, o);
        if ((tid & 31) == 0) warp_s[tid >> 5] = s;
        __syncthreads();
        if (tid == 0) {
            float t = 0.f;
            #pragma unroll
            for (int i = 0; i < 8; i++) t += warp_s[i];
            stat[0] = t * (1.0f / (float)Hn);
        }
        __syncthreads();
        const float mean = stat[0];
        float d0 = v0 - mean, d1 = v1 - mean, d2 = v2 - mean;
        float s2 = d0*d0 + d1*d1 + d2*d2;
        #pragma unroll
        for (int o = 16; o; o >>= 1) s2 += __shfl_xor_sync(0xffffffffu, s2, o);
        if ((tid & 31) == 0) warp_s[tid >> 5] = s2;
        __syncthreads();
        if (tid == 0) {
            float t = 0.f;
            #pragma unroll
            for (int i = 0; i < 8; i++) t += warp_s[i];
            float var = t * (1.0f / (float)Hn);
            float d = var + 1e-12f;
            stat[1] = 1.0f / (d * d);             // ref quirk: (var+eps)^2, no sqrt
        }
        __syncthreads();
        const float inv = stat[1];
        float* xo = g_xhat + (size_t)r * Hn;
        xo[tid]       = d0 * inv;
        xo[tid + 256] = d1 * inv;
        xo[tid + 512] = d2 * inv;
    } else if (bid < NB_STATS + NB_WCLN) {
        int idx = (bid - NB_STATS) * 256 + tid;
        int z = idx / (Hn * Hn);
        int e = idx - z * (Hn * Hn);
        float v = (z ? w_beta : w_gamma)[e];
        __nv_bfloat16 hi = __float2bfloat16(v);
        __nv_bfloat16 lo = __float2bfloat16(v - __bfloat162float(hi));
        if (z) { g_Wb_hi[e] = hi; g_Wb_lo[e] = lo; }
        else   { g_Wg_hi[e] = hi; g_Wg_lo[e] = lo; }
    } else {
        int idx = (bid - NB_STATS - NB_WCLN) * 256 + tid;
        int k  = idx / (Mn * Hn);
        int rm = idx - k * (Mn * Hn);
        int m  = rm / Hn;
        int h  = rm - m * Hn;
        const float* W = (k == 0) ? w_ent : (k == 1) ? w_head : w_tail;
        g_Wth[idx] = __float2half(W[(size_t)h * Mn + m]);
    }
}

// ===========================================================================
// Kernel 2: cln NT GEMM via bf16x3 HMMA -> g_gc / g_bc (3-stage, 64x64)
// ===========================================================================
#define CL_ATB 5120
#define CL_AST (2 * CL_ATB)
#define CL_WOFF (3 * CL_AST)
#define CL_WST (2 * CL_ATB)
#define CL_BIAS (CL_WOFF + 3 * CL_WST)
#define CL_SMEM (CL_BIAS + 256 + 16)

__global__ void __launch_bounds__(256, 3) cln_hmma_kernel(
    const float* __restrict__ gamma, const float* __restrict__ beta)
{
    extern __shared__ __align__(128) char dsm[];
    const uint32_t sB = smem_u32(dsm);
    float* biasS = (float*)(dsm + CL_BIAS);

    const int z  = blockIdx.z;
    const __nv_bfloat16* Wh_g = z ? g_Wb_hi : g_Wg_hi;
    const __nv_bfloat16* Wl_g = z ? g_Wb_lo : g_Wg_lo;
    const float* bias = z ? beta : gamma;
    float* dst        = z ? g_bc : g_gc;

    const int r0 = blockIdx.x * 64;
    const int c0 = blockIdx.y * 64;
    const int tid  = threadIdx.x;
    const int wid  = tid >> 5;
    const int lane = tid & 31;
    const int g    = lane >> 2;
    const int tg   = lane & 3;
    const int wm   = wid >> 1, wn = wid & 1;

    if (tid < 64) biasS[tid] = bias[c0 + tid];

    float acc[4][4];
    #pragma unroll
    for (int nt = 0; nt < 4; nt++)
        #pragma unroll
        for (int r = 0; r < 4; r++) acc[nt][r] = 0.f;

    const int lrow  = (tid & 127) >> 1;
    const int fhalf = tid & 1;
    const uint32_t dro = (uint32_t)(lrow * RS + fhalf * 32);
    const bool isA = (tid < 128);

    auto fill = [&](int c) {
        const int s = c % 3;
        const int kc = c * KC;
        if (isA) {
            size_t asrc = (size_t)(r0 + lrow) * Hn + kc + fhalf * 16;
            uint32_t ad = sB + s * CL_AST + dro;
            CP16(ad,                (const char*)(g_seq_hi + asrc));
            CP16(ad + 16,           (const char*)(g_seq_hi + asrc + 8));
            CP16(ad + CL_ATB,       (const char*)(g_seq_lo + asrc));
            CP16(ad + CL_ATB + 16,  (const char*)(g_seq_lo + asrc + 8));
        } else {
            size_t wsrc = (size_t)(c0 + lrow) * Hn + kc + fhalf * 16;
            uint32_t wd = sB + CL_WOFF + s * CL_WST + dro;
            CP16(wd,                (const char*)(Wh_g + wsrc));
            CP16(wd + 16,           (const char*)(Wh_g + wsrc + 8));
            CP16(wd + CL_ATB,       (const char*)(Wl_g + wsrc));
            CP16(wd + CL_ATB + 16,  (const char*)(Wl_g + wsrc + 8));
        }
        CP_COMMIT();
    };

    const uint32_t loff = (uint32_t)(((lane & 7) + ((lane >> 3) & 1) * 8) * RS + (lane >> 4) * 16);

    fill(0);
    fill(1);
    for (int c = 0; c < NCH; ++c) {
        const int s = c % 3;
        if (c == NCH - 1) { CP_WAITG(0); } else { CP_WAITG(1); }
        __syncthreads();
        if (c + 2 < NCH) fill(c + 2);

        const uint32_t aH = sB + s * CL_AST;
        const uint32_t aL = aH + CL_ATB;
        const uint32_t wH = sB + CL_WOFF + s * CL_WST;
        const uint32_t wL = wH + CL_ATB;

        #pragma unroll
        for (int ks = 0; ks < 2; ks++) {
            const uint32_t ko = ks * 32 + loff;
            uint32_t Ah[4], Al[4];
            uint32_t ab = (uint32_t)((wm * 16) * RS) + ko;
            ldmx4(Ah[0], Ah[1], Ah[2], Ah[3], aH + ab);
            ldmx4(Al[0], Al[1], Al[2], Al[3], aL + ab);
            #pragma unroll
            for (int ntp = 0; ntp < 2; ntp++) {
                uint32_t wb = (uint32_t)((wn * 32 + ntp * 16) * RS) + ko;
                uint32_t h0, h1, h2, h3, l0, l1, l2, l3;
                ldmx4(h0, h1, h2, h3, wH + wb);
                ldmx4(l0, l1, l2, l3, wL + wb);
                mma_bf(acc[2*ntp],   Ah, h0, h2);
                mma_bf(acc[2*ntp],   Ah, l0, l2);
                mma_bf(acc[2*ntp],   Al, h0, h2);
                mma_bf(acc[2*ntp+1], Ah, h1, h3);
                mma_bf(acc[2*ntp+1], Ah, l1, l3);
                mma_bf(acc[2*ntp+1], Al, h1, h3);
            }
        }
    }

    {
        const int row = r0 + wm * 16 + g;
        #pragma unroll
        for (int nt = 0; nt < 4; nt++) {
            const int cc = wn * 32 + nt * 8 + tg * 2;
            const float b0v = biasS[cc], b1v = biasS[cc + 1];
            const float* d = acc[nt];
            *(float2*)(dst + (size_t)row * Hn + c0 + cc) =
                make_float2(d[0] + b0v, d[1] + b1v);
            *(float2*)(dst + (size_t)(row + 8) * Hn + c0 + cc) =
                make_float2(d[2] + b0v, d[3] + b1v);
        }
    }
}

// ===========================================================================
// Kernel 3: cmat NN GEMM (fp32) -> g_Cmat
// ===========================================================================
__global__ void __launch_bounds__(256) cmat_gemm_kernel(
    const float* __restrict__ w_ent,  const float* __restrict__ b_ent,
    const float* __restrict__ w_head, const float* __restrict__ b_head,
    const float* __restrict__ w_tail, const float* __restrict__ b_tail)
{
    __shared__ float Ash[64][17];
    __shared__ float Bsh[64][132];
    const int k = blockIdx.y;
    const float* W    = (k == 0) ? w_ent : (k == 1) ? w_head : w_tail;
    const float* bias = (k == 0) ? b_ent : (k == 1) ? b_head : b_tail;
    const int r0 = blockIdx.x * 16;
    const int tid = threadIdx.x;
    const int tx = tid & 15, ty = tid >> 4;
    const int arow = tid & 15, akq = (tid >> 4) * 4;
    const int bk = tid >> 4, bm0 = (tid & 15) * 8;

    float acc[8];
    #pragma unroll
    for (int v = 0; v < 8; v++) acc[v] = 0.f;

    for (int k0 = 0; k0 < Hn; k0 += 64) {
        float4 a = *(const float4*)(g_bc + (size_t)(r0 + arow) * Hn + k0 + akq);
        Ash[akq+0][arow] = a.x; Ash[akq+1][arow] = a.y;
        Ash[akq+2][arow] = a.z; Ash[akq+3][arow] = a.w;
        #pragma unroll
        for (int rr = 0; rr < 4; rr++) {
            const float4* bp = (const float4*)(W + (size_t)(k0 + bk + rr*16) * Mn + bm0);
            *(float4*)&Bsh[bk + rr*16][bm0]     = bp[0];
            *(float4*)&Bsh[bk + rr*16][bm0 + 4] = bp[1];
        }
        __syncthreads();
        #pragma unroll
        for (int kk = 0; kk < 64; kk++) {
            float a0 = Ash[kk][ty];
            #pragma unroll
            for (int v = 0; v < 8; v++) acc[v] += a0 * Bsh[kk][tx + 16*v];
        }
        __syncthreads();
    }
    {
        int rr = r0 + ty;
        #pragma unroll
        for (int v = 0; v < 8; v++) {
            int cc = tx + 16*v;
            g_Cmat[((size_t)k * (Bn*Sn) + rr) * Mn + cc] = acc[v] + bias[cc];
        }
    }
}

// ===========================================================================
// Kernel 3b: abuild -> A fp16 per (b,i); vectorized (gc row in regs, float4)
// ===========================================================================
__global__ void __launch_bounds__(192) abuild_kernel() {
    const int pid = blockIdx.x;            // b*128 + i
    const int i = pid & 127;
    const int J0 = (i >> 5) << 5;
    const int Rq = (128 - J0) >> 2;
    const int j0 = J0 + blockIdx.y * Rq;
    const int b = pid >> 7;
    const int h = threadIdx.x * 4;
    const float4 gv = *(const float4*)(g_gc + (size_t)pid * Hn + h);
    for (int jr = 0; jr < Rq; jr++) {
        const int j = j0 + jr;
        const float4 x = *(const float4*)(g_xhat + ((size_t)b * Sn + j) * Hn + h);
        __half2 a0 = __floats2half2_rn(x.x * gv.x, x.y * gv.y);
        __half2 a1 = __floats2half2_rn(x.z * gv.z, x.w * gv.w);
        uint2 v;
        v.x = *(uint32_t*)&a0;
        v.y = *(uint32_t*)&a1;
        *(uint2*)(g_Ap + ((size_t)pid * Sn + j) * Hn + h) = v;
    }
}

// ===========================================================================
// Kernel 4: pair GEMM — fp16 HMMA, complementary i-pairing, uniform MT=5.
//   Grid (3, 512): x = head, y = b*64 + q.
//   q<32: (i1=q, J01=0, R1=128) + (i2=q+96, J02=96);
//   else: (i1=q, J01=32, R1=96) + (i2=q+32, J02=64).  R1+R2 = 160 always.
//   One shared W stream per CTA (L2 traffic halved), 4-stage ring,
//   one barrier per 2 chunks, fills right after the barrier.
// ===========================================================================
#define P_WOFF 1024
#define P_ATB (160 * RS)                   // 12800
#define P_AOFF (1024 + 4 * WTB)            // 41984
#define PAIR_SMEM (P_AOFF + 4 * P_ATB + 64)

__global__ void __launch_bounds__(256, 2) pair_f16_all(float* __restrict__ out) {
    extern __shared__ __align__(128) char dsm[];
    const uint32_t sB = smem_u32(dsm);
    float* cmS = (float*)dsm;              // [2][128]

    const int tid  = threadIdx.x;
    const int wid  = tid >> 5;
    const int lane = tid & 31;
    const int g    = lane >> 2;
    const int tg   = lane & 3;
    const int wn   = wid & 3;              // 4 n-warps x 32 cols
    const int wm   = wid >> 2;             // 2 m-warps x 80 rows
    const int head = blockIdx.x;
    const int b    = blockIdx.y >> 6;
    const int q    = blockIdx.y & 63;

    const int i1  = q;
    const int i2  = (q < 32) ? q + 96 : q + 32;
    const int J01 = (q < 32) ? 0 : 32;
    const int J02 = (q < 32) ? 96 : 64;
    const int R1  = 128 - J01;

    if (tid < 128)
        cmS[tid] = g_Cmat[((size_t)head * (Bn*Sn) + b * Sn + i1) * Mn + tid];
    else
        cmS[tid] = g_Cmat[((size_t)head * (Bn*Sn) + b * Sn + i2) * Mn + (tid - 128)];
    // visibility covered by first mainloop barrier (epilogue reads only)

    float acc[5][4][4];
    #pragma unroll
    for (int mt = 0; mt < 5; mt++)
        #pragma unroll
        for (int nt = 0; nt < 4; nt++)
            #pragma unroll
            for (int r = 0; r < 4; r++) acc[mt][nt][r] = 0.f;

    const int r0    = tid >> 1;
    const int fhalf = tid & 1;
    const uint32_t dro1 = (uint32_t)(r0 * RS + fhalf * 32);
    const uint32_t dro2 = (uint32_t)((r0 + 128) * RS + fhalf * 32);

    const __half* A1 = g_Ap + (size_t)(b * Sn + i1) * Sn * Hn;
    const __half* A2 = g_Ap + (size_t)(b * Sn + i2) * Sn * Hn;
    const __half* srcA1 = ((r0 < R1) ? (A1 + (size_t)(J01 + r0) * Hn)
                                     : (A2 + (size_t)(J02 + r0 - R1) * Hn)) + fhalf * 16;
    const __half* srcA2 = A2 + (size_t)(J02 + r0 + 128 - R1) * Hn + fhalf * 16;  // tid<64 only
    const __half* wbase = g_Wth + (size_t)(head * Mn + r0) * Hn + fhalf * 16;

    auto fill = [&](int c) {
        const int s = c & 3;
        const int kc = c * KC;
        uint32_t wd = sB + P_WOFF + s * WTB + dro1;
        CP16(wd,      (const char*)(wbase + kc));
        CP16(wd + 16, (const char*)(wbase + kc + 8));
        uint32_t ad = sB + P_AOFF + s * P_ATB + dro1;
        CP16(ad,      (const char*)(srcA1 + kc));
        CP16(ad + 16, (const char*)(srcA1 + kc + 8));
        if (tid < 64) {
            uint32_t ad2 = sB + P_AOFF + s * P_ATB + dro2;
            CP16(ad2,      (const char*)(srcA2 + kc));
            CP16(ad2 + 16, (const char*)(srcA2 + kc + 8));
        }
        CP_COMMIT();
    };

    const uint32_t loff = (uint32_t)(((lane & 7) + ((lane >> 3) & 1) * 8) * RS + (lane >> 4) * 16);
    const uint32_t mrowb = (uint32_t)(wm * 80);

    auto domma = [&](int c) {
        const int s = c & 3;
        const uint32_t aB = sB + P_AOFF + s * P_ATB;
        const uint32_t wB = sB + P_WOFF + s * WTB;
        #pragma unroll
        for (int ks = 0; ks < 2; ks++) {
            const uint32_t ko = ks * 32 + loff;
            uint32_t Ah[5][4];
            #pragma unroll
            for (int mt = 0; mt < 5; mt++) {
                uint32_t ab = (mrowb + mt * 16) * RS + ko;
                ldmx4(Ah[mt][0], Ah[mt][1], Ah[mt][2], Ah[mt][3], aB + ab);
            }
            #pragma unroll
            for (int ntp = 0; ntp < 2; ntp++) {
                uint32_t wb = (uint32_t)((wn * 32 + ntp * 16) * RS) + ko;
                uint32_t h0, h1, h2, h3;
                ldmx4(h0, h1, h2, h3, wB + wb);
                #pragma unroll
                for (int mt = 0; mt < 5; mt++) {
                    mma_fp16(acc[mt][2*ntp],   Ah[mt], h0, h2);
                    mma_fp16(acc[mt][2*ntp+1], Ah[mt], h1, h3);
                }
            }
        }
    };

    fill(0);
    fill(1);
    for (int t = 0; t < NCH / 2; ++t) {
        const int c0 = 2 * t, c1 = 2 * t + 1;
        CP_WAITG(0);
        __syncthreads();
        if (c0 + 2 < NCH) { fill(c0 + 2); fill(c0 + 3); }
        domma(c0);
        domma(c1);
    }

    // epilogue: map 160-row tile back to (i1 region, i2 region)
    const int po1 = i1 * Sn - (i1 * (i1 - 1)) / 2 - i1;
    const int po2 = i2 * Sn - (i2 * (i2 - 1)) / 2 - i2;
    const size_t hb = (size_t)(head * Bn + b) * Pn;
    #pragma unroll
    for (int mt = 0; mt < 5; mt++) {
        const int rb = wm * 80 + mt * 16;
        const bool reg2 = (rb >= R1);
        const int jb   = reg2 ? (J02 + rb - R1) : (J01 + rb);
        const int ii   = reg2 ? i2 : i1;
        const int po   = reg2 ? po2 : po1;
        const float* cm = cmS + (reg2 ? 128 : 0);
        const int j0r = jb + g;
        #pragma unroll
        for (int nt = 0; nt < 4; nt++) {
            const int m = wn * 32 + nt * 8 + tg * 2;
            const float cm0 = cm[m], cm1 = cm[m + 1];
            const float* d = acc[mt][nt];
            if (j0r >= ii) {
                *(float2*)(out + (hb + (size_t)(po + j0r)) * Mn + m) =
                    make_float2(tanh_fast(d[0] + cm0), tanh_fast(d[1] + cm1));
            }
            const int j1r = j0r + 8;
            if (j1r >= ii) {
                *(float2*)(out + (hb + (size_t)(po + j1r)) * Mn + m) =
                    make_float2(tanh_fast(d[2] + cm0), tanh_fast(d[3] + cm1));
            }
        }
    }
}

// ===========================================================================
extern "C" void kernel_launch(void* const* d_in, const int* in_sizes, int n_in,
                              void* d_out, int out_size) {
    (void)in_sizes; (void)n_in; (void)out_size;
    const float* seq     = (const float*)d_in[0];
    const float* gamma   = (const float*)d_in[1];
    const float* beta    = (const float*)d_in[2];
    const float* w_beta  = (const float*)d_in[3];
    const float* w_gamma = (const float*)d_in[4];
    const float* w_ent   = (const float*)d_in[5];
    const float* b_ent   = (const float*)d_in[6];
    const float* w_head  = (const float*)d_in[7];
    const float* b_head  = (const float*)d_in[8];
    const float* w_tail  = (const float*)d_in[9];
    const float* b_tail  = (const float*)d_in[10];
    float* out = (float*)d_out;

    cudaFuncSetAttribute(cln_hmma_kernel,
                         cudaFuncAttributeMaxDynamicSharedMemorySize, CL_SMEM);
    cudaFuncSetAttribute(pair_f16_all,
                         cudaFuncAttributeMaxDynamicSharedMemorySize, PAIR_SMEM);

    prep_kernel<<<NB_STATS + NB_WCLN + NB_WPROJ, 256>>>(
        seq, w_gamma, w_beta, w_ent, w_head, w_tail);
    cln_hmma_kernel<<<dim3(16, 12, 2), 256, CL_SMEM>>>(gamma, beta);
    cmat_gemm_kernel<<<dim3(64, 3), 256>>>(w_ent, b_ent, w_head, b_head, w_tail, b_tail);
    abuild_kernel<<<dim3(1024, 4), 192>>>();
    pair_f16_all<<<dim3(3, 512), 256, PAIR_SMEM>>>(out);
}

// round 15
// speedup vs baseline: 1.2279x; 1.0578x over previous
#include <cuda_runtime.h>
#include <cuda_bf16.h>
#include <cuda_fp16.h>
#include <math.h>
#include <stdint.h>

// Problem constants: B=8, S=128, H=768, M=128, P = S(S+1)/2 = 8256
#define Bn 8
#define Sn 128
#define Hn 768
#define Mn 128
#define Pn 8256

// Scratch (__device__ globals; allocation-free rule)
__device__ float g_xhat[Bn*Sn*Hn];                         // (x-mean)/(var+eps)^2
__device__ float g_gc  [Bn*Sn*Hn];                         // seq @ w_gamma^T + gamma
__device__ float g_bc  [Bn*Sn*Hn];                         // seq @ w_beta^T  + beta
__device__ float g_Cmat[3*Bn*Sn*Mn];                       // bc @ W_k + bias_k
__device__ __align__(16) __half g_Wth[3*Mn*Hn];            // W_k^T fp16 [k][m][h]
__device__ __align__(16) __half g_Ap[100663296];           // A fp16 [(b,i)][j][h]
__device__ __align__(16) __half g_seq_h[Bn*Sn*Hn];         // seq fp16 (cln)
__device__ __align__(16) __half g_Wg_h[Hn*Hn];             // w_gamma fp16 [o][h]
__device__ __align__(16) __half g_Wb_h[Hn*Hn];             // w_beta  fp16 [o][h]

// ---------------------------------------------------------------------------
__device__ __forceinline__ uint32_t smem_u32(const void* p) {
    uint32_t a;
    asm("{ .reg .u64 t; cvta.to.shared.u64 t, %1; cvt.u32.u64 %0, t; }" : "=r"(a) : "l"(p));
    return a;
}
__device__ __forceinline__ void ldmx4(uint32_t& r0, uint32_t& r1, uint32_t& r2, uint32_t& r3,
                                      uint32_t a) {
    asm volatile("ldmatrix.sync.aligned.m8n8.x4.shared.b16 {%0,%1,%2,%3}, [%4];"
                 : "=r"(r0), "=r"(r1), "=r"(r2), "=r"(r3) : "r"(a));
}
__device__ __forceinline__ void mma_fp16(float* d, const uint32_t* a, uint32_t b0, uint32_t b1) {
    asm volatile(
        "mma.sync.aligned.m16n8k16.row.col.f32.f16.f16.f32 "
        "{%0,%1,%2,%3},{%4,%5,%6,%7},{%8,%9},{%0,%1,%2,%3};"
        : "+f"(d[0]), "+f"(d[1]), "+f"(d[2]), "+f"(d[3])
        : "r"(a[0]), "r"(a[1]), "r"(a[2]), "r"(a[3]), "r"(b0), "r"(b1));
}
#define CP16(dst, src) \
    asm volatile("cp.async.cg.shared.global [%0], [%1], 16;" :: "r"(dst), "l"(src) : "memory")
#define CP_COMMIT() asm volatile("cp.async.commit_group;" ::: "memory")
#define CP_WAITG(n) asm volatile("cp.async.wait_group %0;" :: "n"(n) : "memory")

__device__ __forceinline__ float tanh_fast(float x) {
    float ax = fabsf(x);
    float e  = __expf(2.0f * ax);
    float r  = 1.0f - 2.0f / (e + 1.0f);
    return copysignf(r, x);
}

#define RS 80                      // smem row stride: 64B data + 16B pad
#define KC 32
#define NCH 24                     // 768/32
#define WTB (128 * RS)             // 10240

// ===========================================================================
// Kernel 1 (merged prep): stats+seq fp16 / cln weight fp16 / proj fp16
// ===========================================================================
#define NB_STATS 1024
#define NB_WCLN  2304              // 2*768*768 / (256*2)
#define NB_WPROJ 1152

__global__ void __launch_bounds__(256) prep_kernel(
    const float* __restrict__ seq,
    const float* __restrict__ w_gamma, const float* __restrict__ w_beta,
    const float* __restrict__ w_ent,   const float* __restrict__ w_head,
    const float* __restrict__ w_tail)
{
    __shared__ float warp_s[8];
    __shared__ float stat[2];
    const int bid = blockIdx.x;
    const int tid = threadIdx.x;

    if (bid < NB_STATS) {
        const int r = bid;
        const float* x = seq + (size_t)r * Hn;
        float v0 = x[tid], v1 = x[tid + 256], v2 = x[tid + 512];
        g_seq_h[(size_t)r*Hn + tid]       = __float2half(v0);
        g_seq_h[(size_t)r*Hn + tid + 256] = __float2half(v1);
        g_seq_h[(size_t)r*Hn + tid + 512] = __float2half(v2);

        float s = v0 + v1 + v2;
        #pragma unroll
        for (int o = 16; o; o >>= 1) s += __shfl_xor_sync(0xffffffffu, s, o);
        if ((tid & 31) == 0) warp_s[tid >> 5] = s;
        __syncthreads();
        if (tid == 0) {
            float t = 0.f;
            #pragma unroll
            for (int i = 0; i < 8; i++) t += warp_s[i];
            stat[0] = t * (1.0f / (float)Hn);
        }
        __syncthreads();
        const float mean = stat[0];
        float d0 = v0 - mean, d1 = v1 - mean, d2 = v2 - mean;
        float s2 = d0*d0 + d1*d1 + d2*d2;
        #pragma unroll
        for (int o = 16; o; o >>= 1) s2 += __shfl_xor_sync(0xffffffffu, s2, o);
        if ((tid & 31) == 0) warp_s[tid >> 5] = s2;
        __syncthreads();
        if (tid == 0) {
            float t = 0.f;
            #pragma unroll
            for (int i = 0; i < 8; i++) t += warp_s[i];
            float var = t * (1.0f / (float)Hn);
            float d = var + 1e-12f;
            stat[1] = 1.0f / (d * d);             // ref quirk: (var+eps)^2, no sqrt
        }
        __syncthreads();
        const float inv = stat[1];
        float* xo = g_xhat + (size_t)r * Hn;
        xo[tid]       = d0 * inv;
        xo[tid + 256] = d1 * inv;
        xo[tid + 512] = d2 * inv;
    } else if (bid < NB_STATS + NB_WCLN) {
        int idx = ((bid - NB_STATS) * 256 + tid) * 2;     // even; pairs never straddle z
        int z = idx / (Hn * Hn);
        int e = idx - z * (Hn * Hn);
        const float* src = z ? w_beta : w_gamma;
        __half2 v = __floats2half2_rn(src[e], src[e + 1]);
        __half* dst = z ? g_Wb_h : g_Wg_h;
        *(__half2*)(dst + e) = v;
    } else {
        int idx = (bid - NB_STATS - NB_WCLN) * 256 + tid;
        int k  = idx / (Mn * Hn);
        int rm = idx - k * (Mn * Hn);
        int m  = rm / Hn;
        int h  = rm - m * Hn;
        const float* W = (k == 0) ? w_ent : (k == 1) ? w_head : w_tail;
        g_Wth[idx] = __float2half(W[(size_t)h * Mn + m]);
    }
}

// ===========================================================================
// Kernel 2: cln NT GEMM via single-pass fp16 HMMA -> g_gc / g_bc
//   64x64 tiles, 3-stage ring, one barrier per chunk; ~31 KB smem.
// ===========================================================================
#define CL_TB 5120                          // one 64-row tile (A or W)
#define CL_ST (2 * CL_TB)                   // stage = A + W
#define CL_BIAS (3 * CL_ST)                 // 30720
#define CL_SMEM (CL_BIAS + 256 + 16)

__global__ void __launch_bounds__(256, 4) cln_hmma_kernel(
    const float* __restrict__ gamma, const float* __restrict__ beta)
{
    extern __shared__ __align__(128) char dsm[];
    const uint32_t sB = smem_u32(dsm);
    float* biasS = (float*)(dsm + CL_BIAS);

    const int z  = blockIdx.z;
    const __half* Wf = z ? g_Wb_h : g_Wg_h;
    const float* bias = z ? beta : gamma;
    float* dst        = z ? g_bc : g_gc;

    const int r0 = blockIdx.x * 64;
    const int c0 = blockIdx.y * 64;
    const int tid  = threadIdx.x;
    const int wid  = tid >> 5;
    const int lane = tid & 31;
    const int g    = lane >> 2;
    const int tg   = lane & 3;
    const int wm   = wid >> 1, wn = wid & 1;

    if (tid < 64) biasS[tid] = bias[c0 + tid];

    float acc[4][4];
    #pragma unroll
    for (int nt = 0; nt < 4; nt++)
        #pragma unroll
        for (int r = 0; r < 4; r++) acc[nt][r] = 0.f;

    const int lrow  = (tid & 127) >> 1;
    const int fhalf = tid & 1;
    const uint32_t dro = (uint32_t)(lrow * RS + fhalf * 32);
    const bool isA = (tid < 128);

    auto fill = [&](int c) {
        const int s = c % 3;
        const int kc = c * KC;
        if (isA) {
            size_t asrc = (size_t)(r0 + lrow) * Hn + kc + fhalf * 16;
            uint32_t ad = sB + s * CL_ST + dro;
            CP16(ad,      (const char*)(g_seq_h + asrc));
            CP16(ad + 16, (const char*)(g_seq_h + asrc + 8));
        } else {
            size_t wsrc = (size_t)(c0 + lrow) * Hn + kc + fhalf * 16;
            uint32_t wd = sB + s * CL_ST + CL_TB + dro;
            CP16(wd,      (const char*)(Wf + wsrc));
            CP16(wd + 16, (const char*)(Wf + wsrc + 8));
        }
        CP_COMMIT();
    };

    const uint32_t loff = (uint32_t)(((lane & 7) + ((lane >> 3) & 1) * 8) * RS + (lane >> 4) * 16);

    fill(0);
    fill(1);
    for (int c = 0; c < NCH; ++c) {
        const int s = c % 3;
        if (c == NCH - 1) { CP_WAITG(0); } else { CP_WAITG(1); }
        __syncthreads();
        if (c + 2 < NCH) fill(c + 2);

        const uint32_t aB = sB + s * CL_ST;
        const uint32_t wB = aB + CL_TB;

        #pragma unroll
        for (int ks = 0; ks < 2; ks++) {
            const uint32_t ko = ks * 32 + loff;
            uint32_t Ah[4];
            uint32_t ab = (uint32_t)((wm * 16) * RS) + ko;
            ldmx4(Ah[0], Ah[1], Ah[2], Ah[3], aB + ab);
            #pragma unroll
            for (int ntp = 0; ntp < 2; ntp++) {
                uint32_t wb = (uint32_t)((wn * 32 + ntp * 16) * RS) + ko;
                uint32_t h0, h1, h2, h3;
                ldmx4(h0, h1, h2, h3, wB + wb);
                mma_fp16(acc[2*ntp],   Ah, h0, h2);
                mma_fp16(acc[2*ntp+1], Ah, h1, h3);
            }
        }
    }

    {
        const int row = r0 + wm * 16 + g;
        #pragma unroll
        for (int nt = 0; nt < 4; nt++) {
            const int cc = wn * 32 + nt * 8 + tg * 2;
            const float b0v = biasS[cc], b1v = biasS[cc + 1];
            const float* d = acc[nt];
            *(float2*)(dst + (size_t)row * Hn + c0 + cc) =
                make_float2(d[0] + b0v, d[1] + b1v);
            *(float2*)(dst + (size_t)(row + 8) * Hn + c0 + cc) =
                make_float2(d[2] + b0v, d[3] + b1v);
        }
    }
}

// ===========================================================================
// Kernel 3: cmat NN GEMM (fp32) -> g_Cmat  (accuracy anchor; unchanged)
// ===========================================================================
__global__ void __launch_bounds__(256) cmat_gemm_kernel(
    const float* __restrict__ w_ent,  const float* __restrict__ b_ent,
    const float* __restrict__ w_head, const float* __restrict__ b_head,
    const float* __restrict__ w_tail, const float* __restrict__ b_tail)
{
    __shared__ float Ash[64][17];
    __shared__ float Bsh[64][132];
    const int k = blockIdx.y;
    const float* W    = (k == 0) ? w_ent : (k == 1) ? w_head : w_tail;
    const float* bias = (k == 0) ? b_ent : (k == 1) ? b_head : b_tail;
    const int r0 = blockIdx.x * 16;
    const int tid = threadIdx.x;
    const int tx = tid & 15, ty = tid >> 4;
    const int arow = tid & 15, akq = (tid >> 4) * 4;
    const int bk = tid >> 4, bm0 = (tid & 15) * 8;

    float acc[8];
    #pragma unroll
    for (int v = 0; v < 8; v++) acc[v] = 0.f;

    for (int k0 = 0; k0 < Hn; k0 += 64) {
        float4 a = *(const float4*)(g_bc + (size_t)(r0 + arow) * Hn + k0 + akq);
        Ash[akq+0][arow] = a.x; Ash[akq+1][arow] = a.y;
        Ash[akq+2][arow] = a.z; Ash[akq+3][arow] = a.w;
        #pragma unroll
        for (int rr = 0; rr < 4; rr++) {
            const float4* bp = (const float4*)(W + (size_t)(k0 + bk + rr*16) * Mn + bm0);
            *(float4*)&Bsh[bk + rr*16][bm0]     = bp[0];
            *(float4*)&Bsh[bk + rr*16][bm0 + 4] = bp[1];
        }
        __syncthreads();
        #pragma unroll
        for (int kk = 0; kk < 64; kk++) {
            float a0 = Ash[kk][ty];
            #pragma unroll
            for (int v = 0; v < 8; v++) acc[v] += a0 * Bsh[kk][tx + 16*v];
        }
        __syncthreads();
    }
    {
        int rr = r0 + ty;
        #pragma unroll
        for (int v = 0; v < 8; v++) {
            int cc = tx + 16*v;
            g_Cmat[((size_t)k * (Bn*Sn) + rr) * Mn + cc] = acc[v] + bias[cc];
        }
    }
}

// ===========================================================================
// Kernel 3b: abuild -> A fp16 per (b,i); vectorized (gc row in regs, float4)
// ===========================================================================
__global__ void __launch_bounds__(192) abuild_kernel() {
    const int pid = blockIdx.x;            // b*128 + i
    const int i = pid & 127;
    const int J0 = (i >> 5) << 5;
    const int Rq = (128 - J0) >> 2;
    const int j0 = J0 + blockIdx.y * Rq;
    const int b = pid >> 7;
    const int h = threadIdx.x * 4;
    const float4 gv = *(const float4*)(g_gc + (size_t)pid * Hn + h);
    for (int jr = 0; jr < Rq; jr++) {
        const int j = j0 + jr;
        const float4 x = *(const float4*)(g_xhat + ((size_t)b * Sn + j) * Hn + h);
        __half2 a0 = __floats2half2_rn(x.x * gv.x, x.y * gv.y);
        __half2 a1 = __floats2half2_rn(x.z * gv.z, x.w * gv.w);
        uint2 v;
        v.x = *(uint32_t*)&a0;
        v.y = *(uint32_t*)&a1;
        *(uint2*)(g_Ap + ((size_t)pid * Sn + j) * Hn + h) = v;
    }
}

// ===========================================================================
// Kernel 4: pair GEMM — fp16 HMMA, complementary i-pairing, uniform MT=5.
//   Grid (3, 512): x = head, y = b*64 + q.
//   q<32: (i1=q, J01=0, R1=128) + (i2=q+96, J02=96);
//   else: (i1=q, J01=32, R1=96) + (i2=q+32, J02=64).  R1+R2 = 160 always.
// ===========================================================================
#define P_WOFF 1024
#define P_ATB (160 * RS)                   // 12800
#define P_AOFF (1024 + 4 * WTB)            // 41984
#define PAIR_SMEM (P_AOFF + 4 * P_ATB + 64)

__global__ void __launch_bounds__(256, 2) pair_f16_all(float* __restrict__ out) {
    extern __shared__ __align__(128) char dsm[];
    const uint32_t sB = smem_u32(dsm);
    float* cmS = (float*)dsm;              // [2][128]

    const int tid  = threadIdx.x;
    const int wid  = tid >> 5;
    const int lane = tid & 31;
    const int g    = lane >> 2;
    const int tg   = lane & 3;
    const int wn   = wid & 3;              // 4 n-warps x 32 cols
    const int wm   = wid >> 2;             // 2 m-warps x 80 rows
    const int head = blockIdx.x;
    const int b    = blockIdx.y >> 6;
    const int q    = blockIdx.y & 63;

    const int i1  = q;
    const int i2  = (q < 32) ? q + 96 : q + 32;
    const int J01 = (q < 32) ? 0 : 32;
    const int J02 = (q < 32) ? 96 : 64;
    const int R1  = 128 - J01;

    if (tid < 128)
        cmS[tid] = g_Cmat[((size_t)head * (Bn*Sn) + b * Sn + i1) * Mn + tid];
    else
        cmS[tid] = g_Cmat[((size_t)head * (Bn*Sn) + b * Sn + i2) * Mn + (tid - 128)];

    float acc[5][4][4];
    #pragma unroll
    for (int mt = 0; mt < 5; mt++)
        #pragma unroll
        for (int nt = 0; nt < 4; nt++)
            #pragma unroll
            for (int r = 0; r < 4; r++) acc[mt][nt][r] = 0.f;

    const int r0    = tid >> 1;
    const int fhalf = tid & 1;
    const uint32_t dro1 = (uint32_t)(r0 * RS + fhalf * 32);
    const uint32_t dro2 = (uint32_t)((r0 + 128) * RS + fhalf * 32);

    const __half* A1 = g_Ap + (size_t)(b * Sn + i1) * Sn * Hn;
    const __half* A2 = g_Ap + (size_t)(b * Sn + i2) * Sn * Hn;
    const __half* srcA1 = ((r0 < R1) ? (A1 + (size_t)(J01 + r0) * Hn)
                                     : (A2 + (size_t)(J02 + r0 - R1) * Hn)) + fhalf * 16;
    const __half* srcA2 = A2 + (size_t)(J02 + r0 + 128 - R1) * Hn + fhalf * 16;  // tid<64 only
    const __half* wbase = g_Wth + (size_t)(head * Mn + r0) * Hn + fhalf * 16;

    auto fill = [&](int c) {
        const int s = c & 3;
        const int kc = c * KC;
        uint32_t wd = sB + P_WOFF + s * WTB + dro1;
        CP16(wd,      (const char*)(wbase + kc));
        CP16(wd + 16, (const char*)(wbase + kc + 8));
        uint32_t ad = sB + P_AOFF + s * P_ATB + dro1;
        CP16(ad,      (const char*)(srcA1 + kc));
        CP16(ad + 16, (const char*)(srcA1 + kc + 8));
        if (tid < 64) {
            uint32_t ad2 = sB + P_AOFF + s * P_ATB + dro2;
            CP16(ad2,      (const char*)(srcA2 + kc));
            CP16(ad2 + 16, (const char*)(srcA2 + kc + 8));
        }
        CP_COMMIT();
    };

    const uint32_t loff = (uint32_t)(((lane & 7) + ((lane >> 3) & 1) * 8) * RS + (lane >> 4) * 16);
    const uint32_t mrowb = (uint32_t)(wm * 80);

    auto domma = [&](int c) {
        const int s = c & 3;
        const uint32_t aB = sB + P_AOFF + s * P_ATB;
        const uint32_t wB = sB + P_WOFF + s * WTB;
        #pragma unroll
        for (int ks = 0; ks < 2; ks++) {
            const uint32_t ko = ks * 32 + loff;
            uint32_t Ah[5][4];
            #pragma unroll
            for (int mt = 0; mt < 5; mt++) {
                uint32_t ab = (mrowb + mt * 16) * RS + ko;
                ldmx4(Ah[mt][0], Ah[mt][1], Ah[mt][2], Ah[mt][3], aB + ab);
            }
            #pragma unroll
            for (int ntp = 0; ntp < 2; ntp++) {
                uint32_t wb = (uint32_t)((wn * 32 + ntp * 16) * RS) + ko;
                uint32_t h0, h1, h2, h3;
                ldmx4(h0, h1, h2, h3, wB + wb);
                #pragma unroll
                for (int mt = 0; mt < 5; mt++) {
                    mma_fp16(acc[mt][2*ntp],   Ah[mt], h0, h2);
                    mma_fp16(acc[mt][2*ntp+1], Ah[mt], h1, h3);
                }
            }
        }
    };

    fill(0);
    fill(1);
    for (int t = 0; t < NCH / 2; ++t) {
        const int c0 = 2 * t, c1 = 2 * t + 1;
        CP_WAITG(0);
        __syncthreads();
        if (c0 + 2 < NCH) { fill(c0 + 2); fill(c0 + 3); }
        domma(c0);
        domma(c1);
    }

    // epilogue: map 160-row tile back to (i1 region, i2 region)
    const int po1 = i1 * Sn - (i1 * (i1 - 1)) / 2 - i1;
    const int po2 = i2 * Sn - (i2 * (i2 - 1)) / 2 - i2;
    const size_t hb = (size_t)(head * Bn + b) * Pn;
    #pragma unroll
    for (int mt = 0; mt < 5; mt++) {
        const int rb = wm * 80 + mt * 16;
        const bool reg2 = (rb >= R1);
        const int jb   = reg2 ? (J02 + rb - R1) : (J01 + rb);
        const int ii   = reg2 ? i2 : i1;
        const int po   = reg2 ? po2 : po1;
        const float* cm = cmS + (reg2 ? 128 : 0);
        const int j0r = jb + g;
        #pragma unroll
        for (int nt = 0; nt < 4; nt++) {
            const int m = wn * 32 + nt * 8 + tg * 2;
            const float cm0 = cm[m], cm1 = cm[m + 1];
            const float* d = acc[mt][nt];
            if (j0r >= ii) {
                *(float2*)(out + (hb + (size_t)(po + j0r)) * Mn + m) =
                    make_float2(tanh_fast(d[0] + cm0), tanh_fast(d[1] + cm1));
            }
            const int j1r = j0r + 8;
            if (j1r >= ii) {
                *(float2*)(out + (hb + (size_t)(po + j1r)) * Mn + m) =
                    make_float2(tanh_fast(d[2] + cm0), tanh_fast(d[3] + cm1));
            }
        }
    }
}

// ===========================================================================
extern "C" void kernel_launch(void* const* d_in, const int* in_sizes, int n_in,
                              void* d_out, int out_size) {
    (void)in_sizes; (void)n_in; (void)out_size;
    const float* seq     = (const float*)d_in[0];
    const float* gamma   = (const float*)d_in[1];
    const float* beta    = (const float*)d_in[2];
    const float* w_beta  = (const float*)d_in[3];
    const float* w_gamma = (const float*)d_in[4];
    const float* w_ent   = (const float*)d_in[5];
    const float* b_ent   = (const float*)d_in[6];
    const float* w_head  = (const float*)d_in[7];
    const float* b_head  = (const float*)d_in[8];
    const float* w_tail  = (const float*)d_in[9];
    const float* b_tail  = (const float*)d_in[10];
    float* out = (float*)d_out;

    cudaFuncSetAttribute(cln_hmma_kernel,
                         cudaFuncAttributeMaxDynamicSharedMemorySize, CL_SMEM);
    cudaFuncSetAttribute(pair_f16_all,
                         cudaFuncAttributeMaxDynamicSharedMemorySize, PAIR_SMEM);

    prep_kernel<<<NB_STATS + NB_WCLN + NB_WPROJ, 256>>>(
        seq, w_gamma, w_beta, w_ent, w_head, w_tail);
    cln_hmma_kernel<<<dim3(16, 12, 2), 256, CL_SMEM>>>(gamma, beta);
    cmat_gemm_kernel<<<dim3(64, 3), 256>>>(w_ent, b_ent, w_head, b_head, w_tail, b_tail);
    abuild_kernel<<<dim3(1024, 4), 192>>>();
    pair_f16_all<<<dim3(3, 512), 256, PAIR_SMEM>>>(out);
}

// round 17
// speedup vs baseline: 1.6476x; 1.3418x over previous
#include <cuda_runtime.h>
#include <cuda_bf16.h>
#include <cuda_fp16.h>
#include <math.h>
#include <stdint.h>

// Problem constants: B=8, S=128, H=768, M=128, P = S(S+1)/2 = 8256
#define Bn 8
#define Sn 128
#define Hn 768
#define Mn 128
#define Pn 8256

// Scratch (__device__ globals; allocation-free rule)
__device__ float g_xhat[Bn*Sn*Hn];                         // (x-mean)/(var+eps)^2
__device__ float g_gc  [Bn*Sn*Hn];                         // seq @ w_gamma^T + gamma
__device__ float g_Cmat[3*Bn*Sn*Mn];                       // bc @ W_k + bias_k
__device__ __align__(16) __half g_bc_h[Bn*Sn*Hn];          // bc fp16 (for cmat)
__device__ __align__(16) __half g_Wth[3*Mn*Hn];            // W_k^T fp16 [k][m][h]
__device__ __align__(16) __half g_Ap[100663296];           // A fp16 [(b,i)][j][h]
__device__ __align__(16) __half g_seq_h[Bn*Sn*Hn];         // seq fp16 (cln)
__device__ __align__(16) __half g_Wg_h[Hn*Hn];             // w_gamma fp16 [o][h]
__device__ __align__(16) __half g_Wb_h[Hn*Hn];             // w_beta  fp16 [o][h]

// ---------------------------------------------------------------------------
__device__ __forceinline__ uint32_t smem_u32(const void* p) {
    uint32_t a;
    asm("{ .reg .u64 t; cvta.to.shared.u64 t, %1; cvt.u32.u64 %0, t; }" : "=r"(a) : "l"(p));
    return a;
}
__device__ __forceinline__ void ldmx4(uint32_t& r0, uint32_t& r1, uint32_t& r2, uint32_t& r3,
                                      uint32_t a) {
    asm volatile("ldmatrix.sync.aligned.m8n8.x4.shared.b16 {%0,%1,%2,%3}, [%4];"
                 : "=r"(r0), "=r"(r1), "=r"(r2), "=r"(r3) : "r"(a));
}
__device__ __forceinline__ void mma_fp16(float* d, const uint32_t* a, uint32_t b0, uint32_t b1) {
    asm volatile(
        "mma.sync.aligned.m16n8k16.row.col.f32.f16.f16.f32 "
        "{%0,%1,%2,%3},{%4,%5,%6,%7},{%8,%9},{%0,%1,%2,%3};"
        : "+f"(d[0]), "+f"(d[1]), "+f"(d[2]), "+f"(d[3])
        : "r"(a[0]), "r"(a[1]), "r"(a[2]), "r"(a[3]), "r"(b0), "r"(b1));
}
#define CP16(dst, src) \
    asm volatile("cp.async.cg.shared.global [%0], [%1], 16;" :: "r"(dst), "l"(src) : "memory")
#define CP_COMMIT() asm volatile("cp.async.commit_group;" ::: "memory")
#define CP_WAITG(n) asm volatile("cp.async.wait_group %0;" :: "n"(n) : "memory")

__device__ __forceinline__ float tanh_fast(float x) {
    float ax = fabsf(x);
    float e  = __expf(2.0f * ax);
    float r  = 1.0f - 2.0f / (e + 1.0f);
    return copysignf(r, x);
}

#define RS 80                      // smem row stride: 64B data + 16B pad
#define KC 32
#define NCH 24                     // 768/32
#define WTB (128 * RS)             // 10240

// ===========================================================================
// Kernel 1 (merged prep): stats+seq fp16 / cln weight fp16 / proj transpose
// ===========================================================================
#define NB_STATS 1024
#define NB_WCLN  2304              // 2*768*768 / (256*2)
#define NB_WPROJ 72                // 3 * (768/64) * (128/64) tile transposes

__global__ void __launch_bounds__(256) prep_kernel(
    const float* __restrict__ seq,
    const float* __restrict__ w_gamma, const float* __restrict__ w_beta,
    const float* __restrict__ w_ent,   const float* __restrict__ w_head,
    const float* __restrict__ w_tail)
{
    __shared__ float warp_s[8];
    __shared__ float stat[2];
    const int bid = blockIdx.x;
    const int tid = threadIdx.x;

    if (bid < NB_STATS) {
        const int r = bid;
        const float* x = seq + (size_t)r * Hn;
        float v0 = x[tid], v1 = x[tid + 256], v2 = x[tid + 512];
        g_seq_h[(size_t)r*Hn + tid]       = __float2half(v0);
        g_seq_h[(size_t)r*Hn + tid + 256] = __float2half(v1);
        g_seq_h[(size_t)r*Hn + tid + 512] = __float2half(v2);

        float s = v0 + v1 + v2;
        #pragma unroll
        for (int o = 16; o; o >>= 1) s += __shfl_xor_sync(0xffffffffu, s, o);
        if ((tid & 31) == 0) warp_s[tid >> 5] = s;
        __syncthreads();
        if (tid == 0) {
            float t = 0.f;
            #pragma unroll
            for (int i = 0; i < 8; i++) t += warp_s[i];
            stat[0] = t * (1.0f / (float)Hn);
        }
        __syncthreads();
        const float mean = stat[0];
        float d0 = v0 - mean, d1 = v1 - mean, d2 = v2 - mean;
        float s2 = d0*d0 + d1*d1 + d2*d2;
        #pragma unroll
        for (int o = 16; o; o >>= 1) s2 += __shfl_xor_sync(0xffffffffu, s2, o);
        if ((tid & 31) == 0) warp_s[tid >> 5] = s2;
        __syncthreads();
        if (tid == 0) {
            float t = 0.f;
            #pragma unroll
            for (int i = 0; i < 8; i++) t += warp_s[i];
            float var = t * (1.0f / (float)Hn);
            float d = var + 1e-12f;
            stat[1] = 1.0f / (d * d);             // ref quirk: (var+eps)^2, no sqrt
        }
        __syncthreads();
        const float inv = stat[1];
        float* xo = g_xhat + (size_t)r * Hn;
        xo[tid]       = d0 * inv;
        xo[tid + 256] = d1 * inv;
        xo[tid + 512] = d2 * inv;
    } else if (bid < NB_STATS + NB_WCLN) {
        int idx = ((bid - NB_STATS) * 256 + tid) * 2;     // even; pairs never straddle z
        int z = idx / (Hn * Hn);
        int e = idx - z * (Hn * Hn);
        const float* src = z ? w_beta : w_gamma;
        __half2 v = __floats2half2_rn(src[e], src[e + 1]);
        __half* dst = z ? g_Wb_h : g_Wg_h;
        *(__half2*)(dst + e) = v;
    } else {
        // proj weight transpose: 64(h) x 64(m) tile via smem, coalesced both ways
        __shared__ float tileT[64][65];
        int t = bid - NB_STATS - NB_WCLN;     // 0..71
        int k  = t / 24;                      // 3 heads
        int r2 = t - k * 24;
        int h0 = (r2 >> 1) * 64;              // 12 h-tiles
        int m0 = (r2 & 1) * 64;               // 2 m-tiles
        const float* W = (k == 0) ? w_ent : (k == 1) ? w_head : w_tail;
        const int cc = tid & 63, rr4 = tid >> 6;
        #pragma unroll
        for (int it = 0; it < 16; it++) {
            int row = rr4 + it * 4;
            tileT[row][cc] = W[(size_t)(h0 + row) * Mn + m0 + cc];
        }
        __syncthreads();
        #pragma unroll
        for (int it = 0; it < 16; it++) {
            int mrow = rr4 + it * 4;
            g_Wth[(size_t)(k * Mn + m0 + mrow) * Hn + h0 + cc] =
                __float2half(tileT[cc][mrow]);
        }
    }
}

// ===========================================================================
// Kernel 2: cln NT GEMM via single-pass fp16 HMMA -> g_gc / g_bc_h
//   64x64 tiles, 3-stage ring; z=1 (beta path) writes bc as fp16 only.
// ===========================================================================
#define CL_TB 5120                          // one 64-row tile (A or W)
#define CL_ST (2 * CL_TB)                   // stage = A + W
#define CL_BIAS (3 * CL_ST)                 // 30720
#define CL_SMEM (CL_BIAS + 256 + 16)

__global__ void __launch_bounds__(256, 4) cln_hmma_kernel(
    const float* __restrict__ gamma, const float* __restrict__ beta)
{
    extern __shared__ __align__(128) char dsm[];
    const uint32_t sB = smem_u32(dsm);
    float* biasS = (float*)(dsm + CL_BIAS);

    const int z  = blockIdx.z;
    const __half* Wf = z ? g_Wb_h : g_Wg_h;
    const float* bias = z ? beta : gamma;

    const int r0 = blockIdx.x * 64;
    const int c0 = blockIdx.y * 64;
    const int tid  = threadIdx.x;
    const int wid  = tid >> 5;
    const int lane = tid & 31;
    const int g    = lane >> 2;
    const int tg   = lane & 3;
    const int wm   = wid >> 1, wn = wid & 1;

    if (tid < 64) biasS[tid] = bias[c0 + tid];

    float acc[4][4];
    #pragma unroll
    for (int nt = 0; nt < 4; nt++)
        #pragma unroll
        for (int r = 0; r < 4; r++) acc[nt][r] = 0.f;

    const int lrow  = (tid & 127) >> 1;
    const int fhalf = tid & 1;
    const uint32_t dro = (uint32_t)(lrow * RS + fhalf * 32);
    const bool isA = (tid < 128);

    auto fill = [&](int c) {
        const int s = c % 3;
        const int kc = c * KC;
        if (isA) {
            size_t asrc = (size_t)(r0 + lrow) * Hn + kc + fhalf * 16;
            uint32_t ad = sB + s * CL_ST + dro;
            CP16(ad,      (const char*)(g_seq_h + asrc));
            CP16(ad + 16, (const char*)(g_seq_h + asrc + 8));
        } else {
            size_t wsrc = (size_t)(c0 + lrow) * Hn + kc + fhalf * 16;
            uint32_t wd = sB + s * CL_ST + CL_TB + dro;
            CP16(wd,      (const char*)(Wf + wsrc));
            CP16(wd + 16, (const char*)(Wf + wsrc + 8));
        }
        CP_COMMIT();
    };

    const uint32_t loff = (uint32_t)(((lane & 7) + ((lane >> 3) & 1) * 8) * RS + (lane >> 4) * 16);

    fill(0);
    fill(1);
    for (int c = 0; c < NCH; ++c) {
        const int s = c % 3;
        if (c == NCH - 1) { CP_WAITG(0); } else { CP_WAITG(1); }
        __syncthreads();
        if (c + 2 < NCH) fill(c + 2);

        const uint32_t aB = sB + s * CL_ST;
        const uint32_t wB = aB + CL_TB;

        #pragma unroll
        for (int ks = 0; ks < 2; ks++) {
            const uint32_t ko = ks * 32 + loff;
            uint32_t Ah[4];
            uint32_t ab = (uint32_t)((wm * 16) * RS) + ko;
            ldmx4(Ah[0], Ah[1], Ah[2], Ah[3], aB + ab);
            #pragma unroll
            for (int ntp = 0; ntp < 2; ntp++) {
                uint32_t wb = (uint32_t)((wn * 32 + ntp * 16) * RS) + ko;
                uint32_t h0, h1, h2, h3;
                ldmx4(h0, h1, h2, h3, wB + wb);
                mma_fp16(acc[2*ntp],   Ah, h0, h2);
                mma_fp16(acc[2*ntp+1], Ah, h1, h3);
            }
        }
    }

    {
        const int row = r0 + wm * 16 + g;
        #pragma unroll
        for (int nt = 0; nt < 4; nt++) {
            const int cc = wn * 32 + nt * 8 + tg * 2;
            const float b0v = biasS[cc], b1v = biasS[cc + 1];
            const float* d = acc[nt];
            if (z) {
                // bc path: fp16 only (feeds cmat fp16 GEMM)
                *(__half2*)(g_bc_h + (size_t)row * Hn + c0 + cc) =
                    __floats2half2_rn(d[0] + b0v, d[1] + b1v);
                *(__half2*)(g_bc_h + (size_t)(row + 8) * Hn + c0 + cc) =
                    __floats2half2_rn(d[2] + b0v, d[3] + b1v);
            } else {
                *(float2*)(g_gc + (size_t)row * Hn + c0 + cc) =
                    make_float2(d[0] + b0v, d[1] + b1v);
                *(float2*)(g_gc + (size_t)(row + 8) * Hn + c0 + cc) =
                    make_float2(d[2] + b0v, d[3] + b1v);
            }
        }
    }
}

// ===========================================================================
// Kernel 3: cmat via single-pass fp16 HMMA -> g_Cmat
//   ONE NT GEMM: rows = bc_h (1024), cols = 384 (g_Wth rows, 3 heads),
//   64x64 tiles, grid (16, 6). Bias per col n: (n>>7 head)[n&127].
// ===========================================================================
__global__ void __launch_bounds__(256, 4) cmat_hmma_kernel(
    const float* __restrict__ b_ent, const float* __restrict__ b_head,
    const float* __restrict__ b_tail)
{
    extern __shared__ __align__(128) char dsm[];
    const uint32_t sB = smem_u32(dsm);
    float* biasS = (float*)(dsm + CL_BIAS);

    const int r0 = blockIdx.x * 64;
    const int c0 = blockIdx.y * 64;           // global col in [0,384)
    const int tid  = threadIdx.x;
    const int wid  = tid >> 5;
    const int lane = tid & 31;
    const int g    = lane >> 2;
    const int tg   = lane & 3;
    const int wm   = wid >> 1, wn = wid & 1;

    if (tid < 64) {
        int n = c0 + tid;
        const float* bias = (n < 128) ? b_ent : (n < 256) ? b_head : b_tail;
        biasS[tid] = bias[n & 127];
    }

    float acc[4][4];
    #pragma unroll
    for (int nt = 0; nt < 4; nt++)
        #pragma unroll
        for (int r = 0; r < 4; r++) acc[nt][r] = 0.f;

    const int lrow  = (tid & 127) >> 1;
    const int fhalf = tid & 1;
    const uint32_t dro = (uint32_t)(lrow * RS + fhalf * 32);
    const bool isA = (tid < 128);

    auto fill = [&](int c) {
        const int s = c % 3;
        const int kc = c * KC;
        if (isA) {
            size_t asrc = (size_t)(r0 + lrow) * Hn + kc + fhalf * 16;
            uint32_t ad = sB + s * CL_ST + dro;
            CP16(ad,      (const char*)(g_bc_h + asrc));
            CP16(ad + 16, (const char*)(g_bc_h + asrc + 8));
        } else {
            size_t wsrc = (size_t)(c0 + lrow) * Hn + kc + fhalf * 16;   // g_Wth row (c0+lrow)
            uint32_t wd = sB + s * CL_ST + CL_TB + dro;
            CP16(wd,      (const char*)(g_Wth + wsrc));
            CP16(wd + 16, (const char*)(g_Wth + wsrc + 8));
        }
        CP_COMMIT();
    };

    const uint32_t loff = (uint32_t)(((lane & 7) + ((lane >> 3) & 1) * 8) * RS + (lane >> 4) * 16);

    fill(0);
    fill(1);
    for (int c = 0; c < NCH; ++c) {
        const int s = c % 3;
        if (c == NCH - 1) { CP_WAITG(0); } else { CP_WAITG(1); }
        __syncthreads();
        if (c + 2 < NCH) fill(c + 2);

        const uint32_t aB = sB + s * CL_ST;
        const uint32_t wB = aB + CL_TB;

        #pragma unroll
        for (int ks = 0; ks < 2; ks++) {
            const uint32_t ko = ks * 32 + loff;
            uint32_t Ah[4];
            uint32_t ab = (uint32_t)((wm * 16) * RS) + ko;
            ldmx4(Ah[0], Ah[1], Ah[2], Ah[3], aB + ab);
            #pragma unroll
            for (int ntp = 0; ntp < 2; ntp++) {
                uint32_t wb = (uint32_t)((wn * 32 + ntp * 16) * RS) + ko;
                uint32_t h0, h1, h2, h3;
                ldmx4(h0, h1, h2, h3, wB + wb);
                mma_fp16(acc[2*ntp],   Ah, h0, h2);
                mma_fp16(acc[2*ntp+1], Ah, h1, h3);
            }
        }
    }

    {
        const int row = r0 + wm * 16 + g;
        #pragma unroll
        for (int nt = 0; nt < 4; nt++) {
            const int cc = wn * 32 + nt * 8 + tg * 2;
            const int n  = c0 + cc;
            const int kh = n >> 7, m = n & 127;
            const float b0v = biasS[cc], b1v = biasS[cc + 1];
            const float* d = acc[nt];
            *(float2*)(g_Cmat + ((size_t)kh * (Bn*Sn) + row) * Mn + m) =
                make_float2(d[0] + b0v, d[1] + b1v);
            *(float2*)(g_Cmat + ((size_t)kh * (Bn*Sn) + row + 8) * Mn + m) =
                make_float2(d[2] + b0v, d[3] + b1v);
        }
    }
}

// ===========================================================================
// Kernel 3b: abuild -> A fp16 per (b,i); vectorized (gc row in regs, float4)
// ===========================================================================
__global__ void __launch_bounds__(192) abuild_kernel() {
    const int pid = blockIdx.x;            // b*128 + i
    const int i = pid & 127;
    const int J0 = (i >> 5) << 5;
    const int Rq = (128 - J0) >> 2;
    const int j0 = J0 + blockIdx.y * Rq;
    const int b = pid >> 7;
    const int h = threadIdx.x * 4;
    const float4 gv = *(const float4*)(g_gc + (size_t)pid * Hn + h);
    for (int jr = 0; jr < Rq; jr++) {
        const int j = j0 + jr;
        const float4 x = *(const float4*)(g_xhat + ((size_t)b * Sn + j) * Hn + h);
        __half2 a0 = __floats2half2_rn(x.x * gv.x, x.y * gv.y);
        __half2 a1 = __floats2half2_rn(x.z * gv.z, x.w * gv.w);
        uint2 v;
        v.x = *(uint32_t*)&a0;
        v.y = *(uint32_t*)&a1;
        *(uint2*)(g_Ap + ((size_t)pid * Sn + j) * Hn + h) = v;
    }
}

// ===========================================================================
// Kernel 4: pair GEMM — fp16 HMMA, complementary i-pairing, uniform MT=5.
//   Grid (3, 512): x = head, y = b*64 + q.
//   Fills interleaved with the two MMA blocks to spread LSU pressure.
// ===========================================================================
#define P_WOFF 1024
#define P_ATB (160 * RS)                   // 12800
#define P_AOFF (1024 + 4 * WTB)            // 41984
#define PAIR_SMEM (P_AOFF + 4 * P_ATB + 64)

__global__ void __launch_bounds__(256, 2) pair_f16_all(float* __restrict__ out) {
    extern __shared__ __align__(128) char dsm[];
    const uint32_t sB = smem_u32(dsm);
    float* cmS = (float*)dsm;              // [2][128]

    const int tid  = threadIdx.x;
    const int wid  = tid >> 5;
    const int lane = tid & 31;
    const int g    = lane >> 2;
    const int tg   = lane & 3;
    const int wn   = wid & 3;              // 4 n-warps x 32 cols
    const int wm   = wid >> 2;             // 2 m-warps x 80 rows
    const int head = blockIdx.x;
    const int b    = blockIdx.y >> 6;
    const int q    = blockIdx.y & 63;

    const int i1  = q;
    const int i2  = (q < 32) ? q + 96 : q + 32;
    const int J01 = (q < 32) ? 0 : 32;
    const int J02 = (q < 32) ? 96 : 64;
    const int R1  = 128 - J01;

    if (tid < 128)
        cmS[tid] = g_Cmat[((size_t)head * (Bn*Sn) + b * Sn + i1) * Mn + tid];
    else
        cmS[tid] = g_Cmat[((size_t)head * (Bn*Sn) + b * Sn + i2) * Mn + (tid - 128)];

    float acc[5][4][4];
    #pragma unroll
    for (int mt = 0; mt < 5; mt++)
        #pragma unroll
        for (int nt = 0; nt < 4; nt++)
            #pragma unroll
            for (int r = 0; r < 4; r++) acc[mt][nt][r] = 0.f;

    const int r0    = tid >> 1;
    const int fhalf = tid & 1;
    const uint32_t dro1 = (uint32_t)(r0 * RS + fhalf * 32);
    const uint32_t dro2 = (uint32_t)((r0 + 128) * RS + fhalf * 32);

    const __half* A1 = g_Ap + (size_t)(b * Sn + i1) * Sn * Hn;
    const __half* A2 = g_Ap + (size_t)(b * Sn + i2) * Sn * Hn;
    const __half* srcA1 = ((r0 < R1) ? (A1 + (size_t)(J01 + r0) * Hn)
                                     : (A2 + (size_t)(J02 + r0 - R1) * Hn)) + fhalf * 16;
    const __half* srcA2 = A2 + (size_t)(J02 + r0 + 128 - R1) * Hn + fhalf * 16;  // tid<64 only
    const __half* wbase = g_Wth + (size_t)(head * Mn + r0) * Hn + fhalf * 16;

    auto fill = [&](int c) {
        const int s = c & 3;
        const int kc = c * KC;
        uint32_t wd = sB + P_WOFF + s * WTB + dro1;
        CP16(wd,      (const char*)(wbase + kc));
        CP16(wd + 16, (const char*)(wbase + kc + 8));
        uint32_t ad = sB + P_AOFF + s * P_ATB + dro1;
        CP16(ad,      (const char*)(srcA1 + kc));
        CP16(ad + 16, (const char*)(srcA1 + kc + 8));
        if (tid < 64) {
            uint32_t ad2 = sB + P_AOFF + s * P_ATB + dro2;
            CP16(ad2,      (const char*)(srcA2 + kc));
            CP16(ad2 + 16, (const char*)(srcA2 + kc + 8));
        }
        CP_COMMIT();
    };

    const uint32_t loff = (uint32_t)(((lane & 7) + ((lane >> 3) & 1) * 8) * RS + (lane >> 4) * 16);
    const uint32_t mrowb = (uint32_t)(wm * 80);

    auto domma = [&](int c) {
        const int s = c & 3;
        const uint32_t aB = sB + P_AOFF + s * P_ATB;
        const uint32_t wB = sB + P_WOFF + s * WTB;
        #pragma unroll
        for (int ks = 0; ks < 2; ks++) {
            const uint32_t ko = ks * 32 + loff;
            uint32_t Ah[5][4];
            #pragma unroll
            for (int mt = 0; mt < 5; mt++) {
                uint32_t ab = (mrowb + mt * 16) * RS + ko;
                ldmx4(Ah[mt][0], Ah[mt][1], Ah[mt][2], Ah[mt][3], aB + ab);
            }
            #pragma unroll
            for (int ntp = 0; ntp < 2; ntp++) {
                uint32_t wb = (uint32_t)((wn * 32 + ntp * 16) * RS) + ko;
                uint32_t h0, h1, h2, h3;
                ldmx4(h0, h1, h2, h3, wB + wb);
                #pragma unroll
                for (int mt = 0; mt < 5; mt++) {
                    mma_fp16(acc[mt][2*ntp],   Ah[mt], h0, h2);
                    mma_fp16(acc[mt][2*ntp+1], Ah[mt], h1, h3);
                }
            }
        }
    };

    fill(0);
    fill(1);
    for (int t = 0; t < NCH / 2; ++t) {
        const int c0 = 2 * t, c1 = 2 * t + 1;
        CP_WAITG(0);
        __syncthreads();
        if (c0 + 2 < NCH) fill(c0 + 2);
        domma(c0);
        if (c0 + 3 < NCH) fill(c0 + 3);
        domma(c1);
    }

    // epilogue: map 160-row tile back to (i1 region, i2 region)
    const int po1 = i1 * Sn - (i1 * (i1 - 1)) / 2 - i1;
    const int po2 = i2 * Sn - (i2 * (i2 - 1)) / 2 - i2;
    const size_t hb = (size_t)(head * Bn + b) * Pn;
    #pragma unroll
    for (int mt = 0; mt < 5; mt++) {
        const int rb = wm * 80 + mt * 16;
        const bool reg2 = (rb >= R1);
        const int jb   = reg2 ? (J02 + rb - R1) : (J01 + rb);
        const int ii   = reg2 ? i2 : i1;
        const int po   = reg2 ? po2 : po1;
        const float* cm = cmS + (reg2 ? 128 : 0);
        const int j0r = jb + g;
        #pragma unroll
        for (int nt = 0; nt < 4; nt++) {
            const int m = wn * 32 + nt * 8 + tg * 2;
            const float cm0 = cm[m], cm1 = cm[m + 1];
            const float* d = acc[mt][nt];
            if (j0r >= ii) {
                *(float2*)(out + (hb + (size_t)(po + j0r)) * Mn + m) =
                    make_float2(tanh_fast(d[0] + cm0), tanh_fast(d[1] + cm1));
            }
            const int j1r = j0r + 8;
            if (j1r >= ii) {
                *(float2*)(out + (hb + (size_t)(po + j1r)) * Mn + m) =
                    make_float2(tanh_fast(d[2] + cm0), tanh_fast(d[3] + cm1));
            }
        }
    }
}

// ===========================================================================
extern "C" void kernel_launch(void* const* d_in, const int* in_sizes, int n_in,
                              void* d_out, int out_size) {
    (void)in_sizes; (void)n_in; (void)out_size;
    const float* seq     = (const float*)d_in[0];
    const float* gamma   = (const float*)d_in[1];
    const float* beta    = (const float*)d_in[2];
    const float* w_beta  = (const float*)d_in[3];
    const float* w_gamma = (const float*)d_in[4];
    const float* w_ent   = (const float*)d_in[5];
    const float* b_ent   = (const float*)d_in[6];
    const float* w_head  = (const float*)d_in[7];
    const float* b_head  = (const float*)d_in[8];
    const float* w_tail  = (const float*)d_in[9];
    const float* b_tail  = (const float*)d_in[10];
    float* out = (float*)d_out;

    cudaFuncSetAttribute(cln_hmma_kernel,
                         cudaFuncAttributeMaxDynamicSharedMemorySize, CL_SMEM);
    cudaFuncSetAttribute(cmat_hmma_kernel,
                         cudaFuncAttributeMaxDynamicSharedMemorySize, CL_SMEM);
    cudaFuncSetAttribute(pair_f16_all,
                         cudaFuncAttributeMaxDynamicSharedMemorySize, PAIR_SMEM);

    prep_kernel<<<NB_STATS + NB_WCLN + NB_WPROJ, 256>>>(
        seq, w_gamma, w_beta, w_ent, w_head, w_tail);
    cln_hmma_kernel<<<dim3(16, 12, 2), 256, CL_SMEM>>>(gamma, beta);
    cmat_hmma_kernel<<<dim3(16, 6), 256, CL_SMEM>>>(b_ent, b_head, b_tail);
    abuild_kernel<<<dim3(1024, 4), 192>>>();
    pair_f16_all<<<dim3(3, 512), 256, PAIR_SMEM>>>(out);
}